// round 7
// baseline (speedup 1.0000x reference)
#include <cuda_runtime.h>
#include <cuda_fp16.h>
#include <math.h>
#include <stdint.h>

// ---------------------------------------------------------------------------
// Problem constants
// ---------------------------------------------------------------------------
#define R_ALL 49152      // B*M*NVIEW
#define EMBED 1024
#define INDIM 256
#define HID   256
#define BMR   8192       // B*M
#define NSEQ  6
#define G4    1024       // 4*HID
#define LAYERS 3
#define BATCH 32
#define MROWS 256

// Weight arena offsets (elements)
#define WC_OFF   0
#define WIN_OFF  1048576
#define WIH_OFF  1310720
#define WHH_OFF  2097152
#define W_TOTAL  2883584

// ---------------------------------------------------------------------------
// Scratch (device globals: allocation-free, graph-capturable)
// ---------------------------------------------------------------------------
__device__ float g_big [(size_t)R_ALL * EMBED];     // Gin (fp32, gate-interleaved)
__device__ float g_c   [(size_t)BMR * HID];         // cell state
__device__ float g_v   [R_ALL];
__device__ float g_bsum[LAYERS * G4];               // permuted bih+bhh

__device__ __align__(16) __half g_whi[W_TOTAL];     // weight hi (LSTM W gate-interleaved)
__device__ __align__(16) __half g_wlo[W_TOTAL];     // weight lo
__device__ __align__(16) __half g_ach [(size_t)R_ALL * EMBED];  // conv fp16
__device__ __align__(16) __half g_bigh[(size_t)R_ALL * EMBED];  // stage1 out fp16
__device__ __align__(16) __half g_xh  [(size_t)R_ALL * INDIM];  // xseq fp16

// ---------------------------------------------------------------------------
// Helpers
// ---------------------------------------------------------------------------
__device__ __forceinline__ uint32_t smem_u32(const void* p) {
    uint32_t a;
    asm("{ .reg .u64 t; cvta.to.shared.u64 t, %1; cvt.u32.u64 %0, t; }"
        : "=r"(a) : "l"(p));
    return a;
}

#define CP16(dst, src) \
    asm volatile("cp.async.cg.shared.global [%0], [%1], 16;" :: "r"(dst), "l"(src))
#define CP_COMMIT() asm volatile("cp.async.commit_group;")
#define CP_WAIT2()  asm volatile("cp.async.wait_group 2;")

__device__ __forceinline__ void ldmatrix_x4(uint32_t& r0, uint32_t& r1,
                                            uint32_t& r2, uint32_t& r3,
                                            uint32_t addr) {
    asm volatile("ldmatrix.sync.aligned.m8n8.x4.shared.b16 {%0,%1,%2,%3}, [%4];"
                 : "=r"(r0), "=r"(r1), "=r"(r2), "=r"(r3) : "r"(addr));
}

__device__ __forceinline__ void mma_fp16(float* c, const uint32_t* a,
                                         uint32_t b0, uint32_t b1) {
    asm volatile(
        "mma.sync.aligned.m16n8k16.row.col.f32.f16.f16.f32 "
        "{%0,%1,%2,%3}, {%4,%5,%6,%7}, {%8,%9}, {%0,%1,%2,%3};"
        : "+f"(c[0]), "+f"(c[1]), "+f"(c[2]), "+f"(c[3])
        : "r"(a[0]), "r"(a[1]), "r"(a[2]), "r"(a[3]), "r"(b0), "r"(b1));
}

__device__ __forceinline__ float gelu_exact(float x) {
    return 0.5f * x * (1.0f + erff(x * 0.70710678118654752f));
}
__device__ __forceinline__ float sigm(float x) { return 1.0f / (1.0f + expf(-x)); }

// ---------------------------------------------------------------------------
// Prep kernels (3 launches total so ncu's -s 5 lands on a GEMM)
// ---------------------------------------------------------------------------
__global__ void convert_act(const float* __restrict__ src,
                            __half* __restrict__ dst, int n4)
{
    int i = blockIdx.x * blockDim.x + threadIdx.x;
    if (i >= n4) return;
    float4 v = ((const float4*)src)[i];
    __half2* d = (__half2*)(dst + (size_t)i * 4);
    d[0] = __floats2half2_rn(v.x, v.y);
    d[1] = __floats2half2_rn(v.z, v.w);
}

// All four weight tensors -> fp16 hi/lo arena (LSTM weights gate-interleaved)
__global__ void convert_weights(const float* __restrict__ Wc,
                                const float* __restrict__ Win,
                                const float* __restrict__ Wih,
                                const float* __restrict__ Whh,
                                __half* __restrict__ dh,
                                __half* __restrict__ dl)
{
    int id = blockIdx.x * blockDim.x + threadIdx.x;   // one float4 per thread
    if (id >= W_TOTAL / 4) return;
    const float* src;
    size_t doff;
    if (id < 262144) {                       // Wc 1024x1024
        src  = Wc + (size_t)id * 4;
        doff = WC_OFF + (size_t)id * 4;
    } else if (id < 327680) {                // Win 256x1024
        int lid = id - 262144;
        src  = Win + (size_t)lid * 4;
        doff = WIN_OFF + (size_t)lid * 4;
    } else if (id < 524288) {                // Wih 3 x 1024x256, gate-interleave
        int lid = id - 327680;
        int l   = lid >> 16;                 // 65536 f4 per layer
        int rem = lid & 65535;
        int r   = rem >> 6;                  // row 0..1023
        int kk  = (rem & 63) << 2;
        int nr  = (r & 255) * 4 + (r >> 8);
        src  = Wih + (size_t)l * G4 * INDIM + (size_t)r * INDIM + kk;
        doff = WIH_OFF + (size_t)l * G4 * INDIM + (size_t)nr * INDIM + kk;
    } else {                                 // Whh 3 x 1024x256, gate-interleave
        int lid = id - 524288;
        int l   = lid >> 16;
        int rem = lid & 65535;
        int r   = rem >> 6;
        int kk  = (rem & 63) << 2;
        int nr  = (r & 255) * 4 + (r >> 8);
        src  = Whh + (size_t)l * G4 * HID + (size_t)r * HID + kk;
        doff = WHH_OFF + (size_t)l * G4 * HID + (size_t)nr * HID + kk;
    }
    float4 v = *(const float4*)src;
    __half h0 = __float2half(v.x), h1 = __float2half(v.y);
    __half h2 = __float2half(v.z), h3 = __float2half(v.w);
    __half2* ph = (__half2*)(dh + doff);
    __half2* pl = (__half2*)(dl + doff);
    ph[0] = __halves2half2(h0, h1);
    ph[1] = __halves2half2(h2, h3);
    pl[0] = __floats2half2_rn(v.x - __half2float(h0), v.y - __half2float(h1));
    pl[1] = __floats2half2_rn(v.z - __half2float(h2), v.w - __half2float(h3));
}

// bsum[l, u*4+g] = bih[l, g*256+u] + bhh[l, g*256+u]
__global__ void bias_perm(const float* __restrict__ bih,
                          const float* __restrict__ bhh,
                          float* __restrict__ bsum)
{
    int idx = blockIdx.x * blockDim.x + threadIdx.x;
    if (idx >= LAYERS * G4) return;
    int l = idx >> 10;
    int r = idx & 1023;
    int nr = (r & 255) * 4 + (r >> 8);
    bsum[l * G4 + nr] = bih[idx] + bhh[idx];
}

// ---------------------------------------------------------------------------
// GEMM: C[m][n] = sum_k A[m][k]*(Wh[n][k]+Wl[n][k]) (+ epilogue)
// Tile 256x128, warptile 64x64 (8 warps, 4x2). KC=32, 3-stage cp.async.
// SMEM/stage 32KB: A 256x32 fp16 folded into 128 phys rows x 128B
//   (logical row r -> phys row r&127, chunk c -> c + 4*(r>>7));
// B 128 rows x 128B ([32 hi | 32 lo] fp16). XOR swizzle: chunk c at c^(row&7).
//
// MATH 0: val = acc + bias1[n]
// MATH 1: val = D + gelu(acc + bias1[n])
// MATH 4: fused LSTM cell (gate-interleaved cols; D = Gin slice)
// OUT 0: fp32 C;  OUT 1: fp16 C
// ---------------------------------------------------------------------------
#define TILE_M 256
#define TILE_N 128
#define KC 32
#define STAGES 3
#define STG_BYTES 32768          // A 16KB + B 16KB
#define SMEM_DYN (STAGES * STG_BYTES)

template<int MATH, int OUT>
__global__ void __launch_bounds__(256, 1)
fgemm(const __half* __restrict__ A, int lda,
      const __half* __restrict__ Wh, const __half* __restrict__ Wl,
      int ldw, int K,
      float* __restrict__ Cf, __half* __restrict__ Ch, int ldc,
      const float* __restrict__ bias1,
      const float* __restrict__ D, int ldd,
      float* __restrict__ cst, __half* __restrict__ Xh, int t)
{
    extern __shared__ __align__(128) unsigned char dsm[];
    const uint32_t sbase = smem_u32(dsm);

    const int tid  = threadIdx.x;
    const int wid  = tid >> 5;
    const int lane = tid & 31;
    const int wm   = wid & 3;        // warp row: 64 m
    const int wn   = wid >> 2;       // warp col: 64 n
    const int m0   = blockIdx.y * TILE_M;
    const int n0   = blockIdx.x * TILE_N;
    const int KT   = K / KC;

    float acc[4][8][4];
    #pragma unroll
    for (int i = 0; i < 4; i++)
        #pragma unroll
        for (int j = 0; j < 8; j++)
            #pragma unroll
            for (int q = 0; q < 4; q++) acc[i][j][q] = 0.0f;

    auto stage_issue = [&](int kt) {
        if (kt < KT) {
            const uint32_t soff = (uint32_t)(kt % STAGES) * STG_BYTES;
            const int k0 = kt * KC;
            #pragma unroll
            for (int i = 0; i < 4; ++i) {            // A: 1024 16B chunks
                int id  = tid + (i << 8);
                int row = id >> 2, c = id & 3;       // row 0..255
                const __half* src = A + (size_t)(m0 + row) * lda + k0 + (c << 3);
                int p  = row & 127;
                int cc = c + ((row >> 7) << 2);
                uint32_t dst = sbase + soff + (uint32_t)(p * 128)
                             + (uint32_t)((cc ^ (p & 7)) << 4);
                CP16(dst, src);
            }
            #pragma unroll
            for (int i = 0; i < 4; ++i) {            // B: 1024 chunks
                int id  = tid + (i << 8);
                int row = id >> 3, c = id & 7;
                const __half* src = (c < 4)
                    ? Wh + (size_t)(n0 + row) * ldw + k0 + (c << 3)
                    : Wl + (size_t)(n0 + row) * ldw + k0 + ((c - 4) << 3);
                uint32_t dst = sbase + soff + 16384u + (uint32_t)(row * 128)
                             + (uint32_t)((c ^ (row & 7)) << 4);
                CP16(dst, src);
            }
        }
        CP_COMMIT();
    };

    stage_issue(0);
    stage_issue(1);

    const int lrow = lane & 15;
    const int lk3  = (lane >> 4);       // 0/1: k8 half within k16

    for (int kt = 0; kt < KT; ++kt) {
        stage_issue(kt + 2);
        CP_WAIT2();
        __syncthreads();

        const uint32_t aBase = sbase + (uint32_t)(kt % STAGES) * STG_BYTES;
        const uint32_t bBase = aBase + 16384u;

        #pragma unroll
        for (int ks = 0; ks < 2; ++ks) {
            const int cA = ks * 2 + lk3;             // logical A chunk 0..3
            uint32_t af[4][4];
            #pragma unroll
            for (int mt = 0; mt < 4; ++mt) {
                const int gr = wm * 64 + mt * 16 + lrow;   // 0..255
                const int p  = gr & 127;
                const int cc = cA + ((gr >> 7) << 2);
                ldmatrix_x4(af[mt][0], af[mt][1], af[mt][2], af[mt][3],
                            aBase + (uint32_t)(p * 128)
                                  + (uint32_t)((cc ^ (p & 7)) << 4));
            }
            #pragma unroll
            for (int pp = 0; pp < 4; ++pp) {
                const int r = wn * 64 + pp * 16 + lrow;    // 0..127
                const uint32_t rowb = bBase + (uint32_t)(r * 128);
                uint32_t bh0, bh1, bh2, bh3, bl0, bl1, bl2, bl3;
                ldmatrix_x4(bh0, bh1, bh2, bh3,
                            rowb + (uint32_t)((cA ^ (r & 7)) << 4));
                ldmatrix_x4(bl0, bl1, bl2, bl3,
                            rowb + (uint32_t)(((cA + 4) ^ (r & 7)) << 4));
                #pragma unroll
                for (int mt = 0; mt < 4; ++mt) {
                    mma_fp16(acc[mt][2 * pp],     af[mt], bh0, bh2);
                    mma_fp16(acc[mt][2 * pp],     af[mt], bl0, bl2);
                    mma_fp16(acc[mt][2 * pp + 1], af[mt], bh1, bh3);
                    mma_fp16(acc[mt][2 * pp + 1], af[mt], bl1, bl3);
                }
            }
        }
        __syncthreads();
    }

    // ---- epilogue ----
    const int qrow = lane >> 2;            // 0..7
    const int qcol = (lane & 3) << 1;      // 0,2,4,6
    #pragma unroll
    for (int mt = 0; mt < 4; ++mt) {
        const int gm = m0 + wm * 64 + mt * 16 + qrow;
        #pragma unroll
        for (int nt = 0; nt < 8; ++nt) {
            const int gn = n0 + wn * 64 + nt * 8 + qcol;
            float c0 = acc[mt][nt][0], c1 = acc[mt][nt][1];
            float c2 = acc[mt][nt][2], c3 = acc[mt][nt][3];

            if (MATH == 4) {
                // fused LSTM cell (gate-interleaved columns)
                float2 d0 = *(const float2*)(D + (size_t)gm * ldd + gn);
                float2 d1 = *(const float2*)(D + (size_t)(gm + 8) * ldd + gn);
                float v0 = c0 + d0.x, v1 = c1 + d0.y;
                float v2 = c2 + d1.x, v3 = c3 + d1.y;
                float e0 = __shfl_xor_sync(0xFFFFFFFFu, v0, 1);
                float e1 = __shfl_xor_sync(0xFFFFFFFFu, v1, 1);
                float e2 = __shfl_xor_sync(0xFFFFFFFFu, v2, 1);
                float e3 = __shfl_xor_sync(0xFFFFFFFFu, v3, 1);
                float gi, gf, gg, go; int row;
                if (!(lane & 1)) { gi = v0; gf = v1; gg = e0; go = e1; row = gm; }
                else             { gi = e2; gf = e3; gg = v2; go = v3; row = gm + 8; }
                const int u = gn >> 2;
                const size_t co = (size_t)row * HID + u;
                float cp = cst[co];
                float cn = sigm(gf) * cp + sigm(gi) * tanhf(gg);
                float hn = sigm(go) * tanhf(cn);
                cst[co] = cn;
                Xh[((size_t)row * NSEQ + t) * HID + u] = __float2half(hn);
                continue;
            }

            float2 o0, o1;
            if (MATH == 0) {
                float2 b = *(const float2*)(bias1 + gn);
                o0.x = c0 + b.x; o0.y = c1 + b.y;
                o1.x = c2 + b.x; o1.y = c3 + b.y;
            } else { // MATH 1
                float2 b  = *(const float2*)(bias1 + gn);
                float2 d0 = *(const float2*)(D + (size_t)gm * ldd + gn);
                float2 d1 = *(const float2*)(D + (size_t)(gm + 8) * ldd + gn);
                o0.x = d0.x + gelu_exact(c0 + b.x);
                o0.y = d0.y + gelu_exact(c1 + b.y);
                o1.x = d1.x + gelu_exact(c2 + b.x);
                o1.y = d1.y + gelu_exact(c3 + b.y);
            }
            if (OUT == 0) {
                *(float2*)(Cf + (size_t)gm * ldc + gn)       = o0;
                *(float2*)(Cf + (size_t)(gm + 8) * ldc + gn) = o1;
            } else {
                *(__half2*)(Ch + (size_t)gm * ldc + gn) =
                    __floats2half2_rn(o0.x, o0.y);
                *(__half2*)(Ch + (size_t)(gm + 8) * ldc + gn) =
                    __floats2half2_rn(o1.x, o1.y);
            }
        }
    }
}

// ---------------------------------------------------------------------------
// LSTM t=0 cell on interleaved Gin (h0=c0=0)
// ---------------------------------------------------------------------------
__global__ void lstm_t0(const float* __restrict__ G, int ldg,
                        float* __restrict__ cst, __half* __restrict__ Xh)
{
    int idx = blockIdx.x * blockDim.x + threadIdx.x;
    if (idx >= BMR * HID) return;
    int bm = idx >> 8;
    int u  = idx & 255;
    float4 g = *(const float4*)(G + (size_t)bm * ldg + 4 * u);  // i,f,g,o
    float c = sigm(g.x) * tanhf(g.z);
    float h = sigm(g.w) * tanhf(c);
    cst[idx] = c;
    Xh[(size_t)bm * NSEQ * HID + u] = __float2half(h);
}

// ---------------------------------------------------------------------------
// Heads
// ---------------------------------------------------------------------------
__global__ void viewport_kernel(const __half* __restrict__ X,
                                const float* __restrict__ Wv,
                                const float* __restrict__ bv,
                                float* __restrict__ v)
{
    int warp = blockIdx.x * (blockDim.x >> 5) + (threadIdx.x >> 5);
    int lane = threadIdx.x & 31;
    if (warp >= R_ALL) return;
    const __half* x = X + (size_t)warp * HID;
    float s = 0.0f;
    #pragma unroll
    for (int k = lane; k < HID; k += 32)
        s = fmaf(__half2float(x[k]), Wv[k], s);
    #pragma unroll
    for (int o = 16; o > 0; o >>= 1) s += __shfl_down_sync(0xFFFFFFFFu, s, o);
    if (lane == 0) v[warp] = s + bv[0];
}

__global__ void score_kernel(const float* __restrict__ v,
                             const float* __restrict__ Ws,
                             const float* __restrict__ bs,
                             float* __restrict__ out)
{
    __shared__ float red[256];
    int b = blockIdx.x;
    int m = threadIdx.x;
    const float* vb = v + ((size_t)b * MROWS + m) * NSEQ;
    float s = 0.0f;
    #pragma unroll
    for (int n = 0; n < NSEQ; n++) s = fmaf(vb[n], Ws[n], s);
    red[m] = s;
    __syncthreads();
    for (int st = 128; st > 0; st >>= 1) {
        if (m < st) red[m] += red[m + st];
        __syncthreads();
    }
    if (m == 0) out[b] = bs[0] + red[0] * (1.0f / (float)MROWS);
}

// ---------------------------------------------------------------------------
// Host orchestration
// ---------------------------------------------------------------------------
template<typename T>
static T* sym_addr(const void* symbol)
{
    void* p = nullptr;
    cudaGetSymbolAddress(&p, symbol);
    return (T*)p;
}

extern "C" void kernel_launch(void* const* d_in, const int* in_sizes, int n_in,
                              void* d_out, int out_size)
{
    const float* swin = (const float*)d_in[0];
    const float* conv = (const float*)d_in[1];
    const float* Wc   = (const float*)d_in[2];
    const float* bc   = (const float*)d_in[3];
    const float* Win  = (const float*)d_in[4];
    const float* b_in = (const float*)d_in[5];
    const float* Wih  = (const float*)d_in[6];
    const float* Whh  = (const float*)d_in[7];
    const float* bih  = (const float*)d_in[8];
    const float* bhh  = (const float*)d_in[9];
    const float* Wv   = (const float*)d_in[10];
    const float* bv   = (const float*)d_in[11];
    const float* Ws   = (const float*)d_in[12];
    const float* bs   = (const float*)d_in[13];
    float* out = (float*)d_out;

    float*  big  = sym_addr<float>(g_big);
    float*  cbuf = sym_addr<float>(g_c);
    float*  vbuf = sym_addr<float>(g_v);
    float*  bsum = sym_addr<float>(g_bsum);
    __half* whi  = sym_addr<__half>(g_whi);
    __half* wlo  = sym_addr<__half>(g_wlo);
    __half* ach  = sym_addr<__half>(g_ach);
    __half* bigh = sym_addr<__half>(g_bigh);
    __half* xh   = sym_addr<__half>(g_xh);

    cudaFuncSetAttribute(fgemm<1,1>, cudaFuncAttributeMaxDynamicSharedMemorySize, SMEM_DYN);
    cudaFuncSetAttribute(fgemm<0,1>, cudaFuncAttributeMaxDynamicSharedMemorySize, SMEM_DYN);
    cudaFuncSetAttribute(fgemm<0,0>, cudaFuncAttributeMaxDynamicSharedMemorySize, SMEM_DYN);
    cudaFuncSetAttribute(fgemm<4,0>, cudaFuncAttributeMaxDynamicSharedMemorySize, SMEM_DYN);

    const dim3 blk(256);

    // ---- prep (3 launches) ----
    convert_act<<<(R_ALL * EMBED / 4 + 255) / 256, blk>>>(conv, ach, R_ALL * EMBED / 4);
    convert_weights<<<(W_TOTAL / 4 + 255) / 256, blk>>>(Wc, Win, Wih, Whh, whi, wlo);
    bias_perm<<<(LAYERS * G4 + 255) / 256, blk>>>(bih, bhh, bsum);

    // Stage 1: bigh = fp16(swin + gelu(conv @ Wc^T + bc))   K=1024
    {
        dim3 grid(EMBED / TILE_N, R_ALL / TILE_M);
        fgemm<1,1><<<grid, blk, SMEM_DYN>>>(ach, EMBED,
                                            whi + WC_OFF, wlo + WC_OFF, EMBED, EMBED,
                                            nullptr, bigh, EMBED,
                                            bc, swin, EMBED,
                                            nullptr, nullptr, 0);
    }
    // Stage 2: xh = fp16(big @ Win^T + b_in)                K=1024
    {
        dim3 grid(INDIM / TILE_N, R_ALL / TILE_M);
        fgemm<0,1><<<grid, blk, SMEM_DYN>>>(bigh, EMBED,
                                            whi + WIN_OFF, wlo + WIN_OFF, EMBED, EMBED,
                                            nullptr, xh, INDIM,
                                            b_in, nullptr, 0,
                                            nullptr, nullptr, 0);
    }

    for (int l = 0; l < LAYERS; ++l) {
        const __half* Wih_h = whi + WIH_OFF + (size_t)l * G4 * INDIM;
        const __half* Wih_l = wlo + WIH_OFF + (size_t)l * G4 * INDIM;
        const __half* Whh_h = whi + WHH_OFF + (size_t)l * G4 * HID;
        const __half* Whh_l = wlo + WHH_OFF + (size_t)l * G4 * HID;

        // Gin = xseq @ Wih^T + (bih+bhh)  (interleaved cols)  K=256
        {
            dim3 grid(G4 / TILE_N, R_ALL / TILE_M);
            fgemm<0,0><<<grid, blk, SMEM_DYN>>>(xh, INDIM,
                                                Wih_h, Wih_l, INDIM, INDIM,
                                                big, nullptr, G4,
                                                bsum + l * G4, nullptr, 0,
                                                nullptr, nullptr, 0);
        }

        // t = 0: h0 = c0 = 0 -> cell directly on Gin
        lstm_t0<<<(BMR * HID + 255) / 256, blk>>>(big, NSEQ * G4, cbuf, xh);

        // t >= 1: fused recurrent GEMM + cell; A = xseq slot t-1
        for (int t = 1; t < NSEQ; ++t) {
            dim3 grid(G4 / TILE_N, BMR / TILE_M);
            fgemm<4,0><<<grid, blk, SMEM_DYN>>>(xh + (size_t)(t - 1) * HID, NSEQ * HID,
                                                Whh_h, Whh_l, HID, HID,
                                                nullptr, nullptr, 0,
                                                nullptr,
                                                big + (size_t)t * G4, NSEQ * G4,
                                                cbuf, xh, t);
        }
    }

    viewport_kernel<<<R_ALL / 8, blk>>>(xh, Wv, bv, vbuf);
    score_kernel<<<BATCH, blk>>>(vbuf, Ws, bs, out);
    (void)in_sizes; (void)n_in; (void)out_size;
}

// round 8
// speedup vs baseline: 1.2467x; 1.2467x over previous
#include <cuda_runtime.h>
#include <cuda_fp16.h>
#include <math.h>
#include <stdint.h>

// ---------------------------------------------------------------------------
// Problem constants
// ---------------------------------------------------------------------------
#define R_ALL 49152      // B*M*NVIEW
#define EMBED 1024
#define INDIM 256
#define HID   256
#define BMR   8192       // B*M
#define NSEQ  6
#define G4    1024       // 4*HID
#define LAYERS 3
#define BATCH 32
#define MROWS 256

// Weight arena offsets (elements)
#define WC_OFF   0
#define WIN_OFF  1048576
#define WIH_OFF  1310720
#define WHH_OFF  2097152
#define W_TOTAL  2883584

// ---------------------------------------------------------------------------
// Scratch (device globals: allocation-free, graph-capturable)
// ---------------------------------------------------------------------------
__device__ float g_big [(size_t)R_ALL * EMBED];     // Gin (fp32, gate-interleaved)
__device__ float g_c   [(size_t)BMR * HID];         // cell state
__device__ float g_v   [R_ALL];
__device__ float g_bsum[LAYERS * G4];               // permuted bih+bhh

__device__ __align__(16) __half g_whi[W_TOTAL];     // weight hi (LSTM W gate-interleaved)
__device__ __align__(16) __half g_wlo[W_TOTAL];     // weight lo
__device__ __align__(16) __half g_ach [(size_t)R_ALL * EMBED];  // conv fp16
__device__ __align__(16) __half g_bigh[(size_t)R_ALL * EMBED];  // stage1 out fp16
__device__ __align__(16) __half g_xh  [(size_t)R_ALL * INDIM];  // xseq fp16

// ---------------------------------------------------------------------------
// Helpers
// ---------------------------------------------------------------------------
__device__ __forceinline__ uint32_t smem_u32(const void* p) {
    uint32_t a;
    asm("{ .reg .u64 t; cvta.to.shared.u64 t, %1; cvt.u32.u64 %0, t; }"
        : "=r"(a) : "l"(p));
    return a;
}

#define CP16(dst, src) \
    asm volatile("cp.async.cg.shared.global [%0], [%1], 16;" :: "r"(dst), "l"(src))
#define CP_COMMIT() asm volatile("cp.async.commit_group;")
#define CP_WAIT1()  asm volatile("cp.async.wait_group 1;")

__device__ __forceinline__ void ldmatrix_x4(uint32_t& r0, uint32_t& r1,
                                            uint32_t& r2, uint32_t& r3,
                                            uint32_t addr) {
    asm volatile("ldmatrix.sync.aligned.m8n8.x4.shared.b16 {%0,%1,%2,%3}, [%4];"
                 : "=r"(r0), "=r"(r1), "=r"(r2), "=r"(r3) : "r"(addr));
}

__device__ __forceinline__ void mma_fp16(float* c, const uint32_t* a,
                                         uint32_t b0, uint32_t b1) {
    asm volatile(
        "mma.sync.aligned.m16n8k16.row.col.f32.f16.f16.f32 "
        "{%0,%1,%2,%3}, {%4,%5,%6,%7}, {%8,%9}, {%0,%1,%2,%3};"
        : "+f"(c[0]), "+f"(c[1]), "+f"(c[2]), "+f"(c[3])
        : "r"(a[0]), "r"(a[1]), "r"(a[2]), "r"(a[3]), "r"(b0), "r"(b1));
}

__device__ __forceinline__ float gelu_exact(float x) {
    return 0.5f * x * (1.0f + erff(x * 0.70710678118654752f));
}
__device__ __forceinline__ float sigm(float x) { return 1.0f / (1.0f + expf(-x)); }

// ---------------------------------------------------------------------------
// Prep kernels
// ---------------------------------------------------------------------------
__global__ void convert_act(const float* __restrict__ src,
                            __half* __restrict__ dst, int n4)
{
    int i = blockIdx.x * blockDim.x + threadIdx.x;
    if (i >= n4) return;
    float4 v = ((const float4*)src)[i];
    __half2* d = (__half2*)(dst + (size_t)i * 4);
    d[0] = __floats2half2_rn(v.x, v.y);
    d[1] = __floats2half2_rn(v.z, v.w);
}

// All four weight tensors -> fp16 hi/lo arena (LSTM weights gate-interleaved)
__global__ void convert_weights(const float* __restrict__ Wc,
                                const float* __restrict__ Win,
                                const float* __restrict__ Wih,
                                const float* __restrict__ Whh,
                                __half* __restrict__ dh,
                                __half* __restrict__ dl)
{
    int id = blockIdx.x * blockDim.x + threadIdx.x;   // one float4 per thread
    if (id >= W_TOTAL / 4) return;
    const float* src;
    size_t doff;
    if (id < 262144) {                       // Wc 1024x1024
        src  = Wc + (size_t)id * 4;
        doff = WC_OFF + (size_t)id * 4;
    } else if (id < 327680) {                // Win 256x1024
        int lid = id - 262144;
        src  = Win + (size_t)lid * 4;
        doff = WIN_OFF + (size_t)lid * 4;
    } else if (id < 524288) {                // Wih 3 x 1024x256, gate-interleave
        int lid = id - 327680;
        int l   = lid >> 16;
        int rem = lid & 65535;
        int r   = rem >> 6;
        int kk  = (rem & 63) << 2;
        int nr  = (r & 255) * 4 + (r >> 8);
        src  = Wih + (size_t)l * G4 * INDIM + (size_t)r * INDIM + kk;
        doff = WIH_OFF + (size_t)l * G4 * INDIM + (size_t)nr * INDIM + kk;
    } else {                                 // Whh 3 x 1024x256, gate-interleave
        int lid = id - 524288;
        int l   = lid >> 16;
        int rem = lid & 65535;
        int r   = rem >> 6;
        int kk  = (rem & 63) << 2;
        int nr  = (r & 255) * 4 + (r >> 8);
        src  = Whh + (size_t)l * G4 * HID + (size_t)r * HID + kk;
        doff = WHH_OFF + (size_t)l * G4 * HID + (size_t)nr * HID + kk;
    }
    float4 v = *(const float4*)src;
    __half h0 = __float2half(v.x), h1 = __float2half(v.y);
    __half h2 = __float2half(v.z), h3 = __float2half(v.w);
    __half2* ph = (__half2*)(dh + doff);
    __half2* pl = (__half2*)(dl + doff);
    ph[0] = __halves2half2(h0, h1);
    ph[1] = __halves2half2(h2, h3);
    pl[0] = __floats2half2_rn(v.x - __half2float(h0), v.y - __half2float(h1));
    pl[1] = __floats2half2_rn(v.z - __half2float(h2), v.w - __half2float(h3));
}

// bsum[l, u*4+g] = bih[l, g*256+u] + bhh[l, g*256+u]
__global__ void bias_perm(const float* __restrict__ bih,
                          const float* __restrict__ bhh,
                          float* __restrict__ bsum)
{
    int idx = blockIdx.x * blockDim.x + threadIdx.x;
    if (idx >= LAYERS * G4) return;
    int l = idx >> 10;
    int r = idx & 1023;
    int nr = (r & 255) * 4 + (r >> 8);
    bsum[l * G4 + nr] = bih[idx] + bhh[idx];
}

// ---------------------------------------------------------------------------
// GEMM: C[m][n] = sum_k A[m][k]*(Wh[n][k]+Wl[n][k]) (+ epilogue)
// A: fp16 single. W: fp16 hi/lo. 2 MMA products per k16.
// Tile 128x128, warptile 32x64 (8 warps 4x2), KC=64, 2-stage cp.async.
// Inner loop reordered: 16 hi MMAs over 16 distinct accs, then 16 lo MMAs
// (same-acc reuse distance 16 >> HMMA latency; was 1 -> tensor pipe ~50%).
//
// MATH 0: val = acc + bias1[n]
// MATH 1: val = D + gelu(acc + bias1[n])
// MATH 4: fused LSTM cell (gate-interleaved cols; D = Gin slice)
// OUT 0: fp32 C;  OUT 1: fp16 C
// ---------------------------------------------------------------------------
#define TILE_M 128
#define TILE_N 128
#define KC2 64
#define STG_BYTES 49152          // A 16KB + B 32KB
#define SMEM_DYN (2 * STG_BYTES)

template<int MATH, int OUT>
__global__ void __launch_bounds__(256, 2)
fgemm(const __half* __restrict__ A, int lda,
      const __half* __restrict__ Wh, const __half* __restrict__ Wl,
      int ldw, int K,
      float* __restrict__ Cf, __half* __restrict__ Ch, int ldc,
      const float* __restrict__ bias1,
      const float* __restrict__ D, int ldd,
      float* __restrict__ cst, __half* __restrict__ Xh, int t)
{
    extern __shared__ __align__(128) unsigned char dsm[];
    const uint32_t sbase = smem_u32(dsm);

    const int tid  = threadIdx.x;
    const int wid  = tid >> 5;
    const int lane = tid & 31;
    const int wm   = wid & 3;        // warp row: 32 m
    const int wn   = wid >> 2;       // warp col: 64 n
    const int m0   = blockIdx.y * TILE_M;
    const int n0   = blockIdx.x * TILE_N;
    const int KT2  = K / KC2;

    float acc[2][8][4];
    #pragma unroll
    for (int i = 0; i < 2; i++)
        #pragma unroll
        for (int j = 0; j < 8; j++)
            #pragma unroll
            for (int q = 0; q < 4; q++) acc[i][j][q] = 0.0f;

    auto stage_issue = [&](int kt2) {
        if (kt2 < KT2) {
            const uint32_t soff = (uint32_t)(kt2 & 1) * STG_BYTES;
            const int k0 = kt2 * KC2;
            #pragma unroll
            for (int i = 0; i < 4; ++i) {            // A: 1024 16B chunks
                int id  = tid + (i << 8);
                int row = id >> 3, c = id & 7;
                const __half* src = A + (size_t)(m0 + row) * lda + k0 + (c << 3);
                uint32_t dst = sbase + soff + (uint32_t)(row * 128)
                             + (uint32_t)((c ^ (row & 7)) << 4);
                CP16(dst, src);
            }
            #pragma unroll
            for (int i = 0; i < 8; ++i) {            // B: 2048 chunks
                int id  = tid + (i << 8);
                int sub = id >> 10;
                int rid = id & 1023;
                int row = rid >> 3, c = rid & 7;
                int kk  = k0 + sub * 32;
                const __half* src = (c < 4)
                    ? Wh + (size_t)(n0 + row) * ldw + kk + (c << 3)
                    : Wl + (size_t)(n0 + row) * ldw + kk + ((c - 4) << 3);
                uint32_t dst = sbase + soff + 16384u + (uint32_t)(sub << 14)
                             + (uint32_t)(row * 128)
                             + (uint32_t)((c ^ (row & 7)) << 4);
                CP16(dst, src);
            }
        }
        CP_COMMIT();
    };

    stage_issue(0);

    const int lrow = lane & 15;
    const int lk3  = (lane >> 4);       // 0/1: k8 half within k16

    // hoisted per-lane row geometry
    const int arow[2] = { wm * 32 + lrow, wm * 32 + 16 + lrow };
    const int brow[4] = { wn * 64 + lrow,      wn * 64 + 16 + lrow,
                          wn * 64 + 32 + lrow, wn * 64 + 48 + lrow };

    for (int kt2 = 0; kt2 < KT2; ++kt2) {
        stage_issue(kt2 + 1);
        CP_WAIT1();
        __syncthreads();

        const uint32_t aBase = sbase + (uint32_t)(kt2 & 1) * STG_BYTES;

        #pragma unroll
        for (int ks = 0; ks < 4; ++ks) {
            const int chunkA = ks * 2 + lk3;                 // 0..7
            const int sub    = ks >> 1;
            const int chunkB = (ks & 1) * 2 + lk3;           // 0..3 (hi); +4 lo
            const uint32_t bBase = aBase + 16384u + (uint32_t)(sub << 14);

            // A fragments
            uint32_t af[2][4];
            #pragma unroll
            for (int mt = 0; mt < 2; ++mt) {
                const int r = arow[mt];
                ldmatrix_x4(af[mt][0], af[mt][1], af[mt][2], af[mt][3],
                            aBase + (uint32_t)(r * 128)
                                  + (uint32_t)((chunkA ^ (r & 7)) << 4));
            }
            // B hi fragments for all 4 n-pairs
            uint32_t bh[4][4];
            #pragma unroll
            for (int p = 0; p < 4; ++p) {
                const int r = brow[p];
                ldmatrix_x4(bh[p][0], bh[p][1], bh[p][2], bh[p][3],
                            bBase + (uint32_t)(r * 128)
                                  + (uint32_t)((chunkB ^ (r & 7)) << 4));
            }
            // 16 hi MMAs, all distinct accumulators
            #pragma unroll
            for (int p = 0; p < 4; ++p)
                #pragma unroll
                for (int mt = 0; mt < 2; ++mt) {
                    mma_fp16(acc[mt][2 * p],     af[mt], bh[p][0], bh[p][2]);
                    mma_fp16(acc[mt][2 * p + 1], af[mt], bh[p][1], bh[p][3]);
                }
            // B lo fragments
            uint32_t bl[4][4];
            #pragma unroll
            for (int p = 0; p < 4; ++p) {
                const int r = brow[p];
                ldmatrix_x4(bl[p][0], bl[p][1], bl[p][2], bl[p][3],
                            bBase + (uint32_t)(r * 128)
                                  + (uint32_t)(((chunkB + 4) ^ (r & 7)) << 4));
            }
            // 16 lo MMAs
            #pragma unroll
            for (int p = 0; p < 4; ++p)
                #pragma unroll
                for (int mt = 0; mt < 2; ++mt) {
                    mma_fp16(acc[mt][2 * p],     af[mt], bl[p][0], bl[p][2]);
                    mma_fp16(acc[mt][2 * p + 1], af[mt], bl[p][1], bl[p][3]);
                }
        }
        __syncthreads();
    }

    // ---- epilogue ----
    const int qrow = lane >> 2;            // 0..7
    const int qcol = (lane & 3) << 1;      // 0,2,4,6
    #pragma unroll
    for (int mt = 0; mt < 2; ++mt) {
        const int gm = m0 + wm * 32 + mt * 16 + qrow;
        #pragma unroll
        for (int nt = 0; nt < 8; ++nt) {
            const int gn = n0 + wn * 64 + nt * 8 + qcol;
            float c0 = acc[mt][nt][0], c1 = acc[mt][nt][1];
            float c2 = acc[mt][nt][2], c3 = acc[mt][nt][3];

            if (MATH == 4) {
                // fused LSTM cell (gate-interleaved columns)
                float2 d0 = *(const float2*)(D + (size_t)gm * ldd + gn);
                float2 d1 = *(const float2*)(D + (size_t)(gm + 8) * ldd + gn);
                float v0 = c0 + d0.x, v1 = c1 + d0.y;
                float v2 = c2 + d1.x, v3 = c3 + d1.y;
                float e0 = __shfl_xor_sync(0xFFFFFFFFu, v0, 1);
                float e1 = __shfl_xor_sync(0xFFFFFFFFu, v1, 1);
                float e2 = __shfl_xor_sync(0xFFFFFFFFu, v2, 1);
                float e3 = __shfl_xor_sync(0xFFFFFFFFu, v3, 1);
                float gi, gf, gg, go; int row;
                if (!(lane & 1)) { gi = v0; gf = v1; gg = e0; go = e1; row = gm; }
                else             { gi = e2; gf = e3; gg = v2; go = v3; row = gm + 8; }
                const int u = gn >> 2;
                const size_t co = (size_t)row * HID + u;
                float cp = cst[co];
                float cn = sigm(gf) * cp + sigm(gi) * tanhf(gg);
                float hn = sigm(go) * tanhf(cn);
                cst[co] = cn;
                Xh[((size_t)row * NSEQ + t) * HID + u] = __float2half(hn);
                continue;
            }

            float2 o0, o1;
            if (MATH == 0) {
                float2 b = *(const float2*)(bias1 + gn);
                o0.x = c0 + b.x; o0.y = c1 + b.y;
                o1.x = c2 + b.x; o1.y = c3 + b.y;
            } else { // MATH 1
                float2 b  = *(const float2*)(bias1 + gn);
                float2 d0 = *(const float2*)(D + (size_t)gm * ldd + gn);
                float2 d1 = *(const float2*)(D + (size_t)(gm + 8) * ldd + gn);
                o0.x = d0.x + gelu_exact(c0 + b.x);
                o0.y = d0.y + gelu_exact(c1 + b.y);
                o1.x = d1.x + gelu_exact(c2 + b.x);
                o1.y = d1.y + gelu_exact(c3 + b.y);
            }
            if (OUT == 0) {
                *(float2*)(Cf + (size_t)gm * ldc + gn)       = o0;
                *(float2*)(Cf + (size_t)(gm + 8) * ldc + gn) = o1;
            } else {
                *(__half2*)(Ch + (size_t)gm * ldc + gn) =
                    __floats2half2_rn(o0.x, o0.y);
                *(__half2*)(Ch + (size_t)(gm + 8) * ldc + gn) =
                    __floats2half2_rn(o1.x, o1.y);
            }
        }
    }
}

// ---------------------------------------------------------------------------
// LSTM t=0 cell on interleaved Gin (h0=c0=0)
// ---------------------------------------------------------------------------
__global__ void lstm_t0(const float* __restrict__ G, int ldg,
                        float* __restrict__ cst, __half* __restrict__ Xh)
{
    int idx = blockIdx.x * blockDim.x + threadIdx.x;
    if (idx >= BMR * HID) return;
    int bm = idx >> 8;
    int u  = idx & 255;
    float4 g = *(const float4*)(G + (size_t)bm * ldg + 4 * u);  // i,f,g,o
    float c = sigm(g.x) * tanhf(g.z);
    float h = sigm(g.w) * tanhf(c);
    cst[idx] = c;
    Xh[(size_t)bm * NSEQ * HID + u] = __float2half(h);
}

// ---------------------------------------------------------------------------
// Heads
// ---------------------------------------------------------------------------
__global__ void viewport_kernel(const __half* __restrict__ X,
                                const float* __restrict__ Wv,
                                const float* __restrict__ bv,
                                float* __restrict__ v)
{
    int warp = blockIdx.x * (blockDim.x >> 5) + (threadIdx.x >> 5);
    int lane = threadIdx.x & 31;
    if (warp >= R_ALL) return;
    const __half* x = X + (size_t)warp * HID;
    float s = 0.0f;
    #pragma unroll
    for (int k = lane; k < HID; k += 32)
        s = fmaf(__half2float(x[k]), Wv[k], s);
    #pragma unroll
    for (int o = 16; o > 0; o >>= 1) s += __shfl_down_sync(0xFFFFFFFFu, s, o);
    if (lane == 0) v[warp] = s + bv[0];
}

__global__ void score_kernel(const float* __restrict__ v,
                             const float* __restrict__ Ws,
                             const float* __restrict__ bs,
                             float* __restrict__ out)
{
    __shared__ float red[256];
    int b = blockIdx.x;
    int m = threadIdx.x;
    const float* vb = v + ((size_t)b * MROWS + m) * NSEQ;
    float s = 0.0f;
    #pragma unroll
    for (int n = 0; n < NSEQ; n++) s = fmaf(vb[n], Ws[n], s);
    red[m] = s;
    __syncthreads();
    for (int st = 128; st > 0; st >>= 1) {
        if (m < st) red[m] += red[m + st];
        __syncthreads();
    }
    if (m == 0) out[b] = bs[0] + red[0] * (1.0f / (float)MROWS);
}

// ---------------------------------------------------------------------------
// Host orchestration
// ---------------------------------------------------------------------------
template<typename T>
static T* sym_addr(const void* symbol)
{
    void* p = nullptr;
    cudaGetSymbolAddress(&p, symbol);
    return (T*)p;
}

extern "C" void kernel_launch(void* const* d_in, const int* in_sizes, int n_in,
                              void* d_out, int out_size)
{
    const float* swin = (const float*)d_in[0];
    const float* conv = (const float*)d_in[1];
    const float* Wc   = (const float*)d_in[2];
    const float* bc   = (const float*)d_in[3];
    const float* Win  = (const float*)d_in[4];
    const float* b_in = (const float*)d_in[5];
    const float* Wih  = (const float*)d_in[6];
    const float* Whh  = (const float*)d_in[7];
    const float* bih  = (const float*)d_in[8];
    const float* bhh  = (const float*)d_in[9];
    const float* Wv   = (const float*)d_in[10];
    const float* bv   = (const float*)d_in[11];
    const float* Ws   = (const float*)d_in[12];
    const float* bs   = (const float*)d_in[13];
    float* out = (float*)d_out;

    float*  big  = sym_addr<float>(g_big);
    float*  cbuf = sym_addr<float>(g_c);
    float*  vbuf = sym_addr<float>(g_v);
    float*  bsum = sym_addr<float>(g_bsum);
    __half* whi  = sym_addr<__half>(g_whi);
    __half* wlo  = sym_addr<__half>(g_wlo);
    __half* ach  = sym_addr<__half>(g_ach);
    __half* bigh = sym_addr<__half>(g_bigh);
    __half* xh   = sym_addr<__half>(g_xh);

    cudaFuncSetAttribute(fgemm<1,1>, cudaFuncAttributeMaxDynamicSharedMemorySize, SMEM_DYN);
    cudaFuncSetAttribute(fgemm<0,1>, cudaFuncAttributeMaxDynamicSharedMemorySize, SMEM_DYN);
    cudaFuncSetAttribute(fgemm<0,0>, cudaFuncAttributeMaxDynamicSharedMemorySize, SMEM_DYN);
    cudaFuncSetAttribute(fgemm<4,0>, cudaFuncAttributeMaxDynamicSharedMemorySize, SMEM_DYN);

    const dim3 blk(256);

    // ---- prep (3 launches) ----
    convert_act<<<(R_ALL * EMBED / 4 + 255) / 256, blk>>>(conv, ach, R_ALL * EMBED / 4);
    convert_weights<<<(W_TOTAL / 4 + 255) / 256, blk>>>(Wc, Win, Wih, Whh, whi, wlo);
    bias_perm<<<(LAYERS * G4 + 255) / 256, blk>>>(bih, bhh, bsum);

    // Stage 1: bigh = fp16(swin + gelu(conv @ Wc^T + bc))   K=1024
    {
        dim3 grid(EMBED / TILE_N, R_ALL / TILE_M);
        fgemm<1,1><<<grid, blk, SMEM_DYN>>>(ach, EMBED,
                                            whi + WC_OFF, wlo + WC_OFF, EMBED, EMBED,
                                            nullptr, bigh, EMBED,
                                            bc, swin, EMBED,
                                            nullptr, nullptr, 0);
    }
    // Stage 2: xh = fp16(big @ Win^T + b_in)                K=1024
    {
        dim3 grid(INDIM / TILE_N, R_ALL / TILE_M);
        fgemm<0,1><<<grid, blk, SMEM_DYN>>>(bigh, EMBED,
                                            whi + WIN_OFF, wlo + WIN_OFF, EMBED, EMBED,
                                            nullptr, xh, INDIM,
                                            b_in, nullptr, 0,
                                            nullptr, nullptr, 0);
    }

    for (int l = 0; l < LAYERS; ++l) {
        const __half* Wih_h = whi + WIH_OFF + (size_t)l * G4 * INDIM;
        const __half* Wih_l = wlo + WIH_OFF + (size_t)l * G4 * INDIM;
        const __half* Whh_h = whi + WHH_OFF + (size_t)l * G4 * HID;
        const __half* Whh_l = wlo + WHH_OFF + (size_t)l * G4 * HID;

        // Gin = xseq @ Wih^T + (bih+bhh)  (interleaved cols)  K=256
        {
            dim3 grid(G4 / TILE_N, R_ALL / TILE_M);
            fgemm<0,0><<<grid, blk, SMEM_DYN>>>(xh, INDIM,
                                                Wih_h, Wih_l, INDIM, INDIM,
                                                big, nullptr, G4,
                                                bsum + l * G4, nullptr, 0,
                                                nullptr, nullptr, 0);
        }

        // t = 0: h0 = c0 = 0 -> cell directly on Gin
        lstm_t0<<<(BMR * HID + 255) / 256, blk>>>(big, NSEQ * G4, cbuf, xh);

        // t >= 1: fused recurrent GEMM + cell; A = xseq slot t-1
        for (int t = 1; t < NSEQ; ++t) {
            dim3 grid(G4 / TILE_N, BMR / TILE_M);
            fgemm<4,0><<<grid, blk, SMEM_DYN>>>(xh + (size_t)(t - 1) * HID, NSEQ * HID,
                                                Whh_h, Whh_l, HID, HID,
                                                nullptr, nullptr, 0,
                                                nullptr,
                                                big + (size_t)t * G4, NSEQ * G4,
                                                cbuf, xh, t);
        }
    }

    viewport_kernel<<<R_ALL / 8, blk>>>(xh, Wv, bv, vbuf);
    score_kernel<<<BATCH, blk>>>(vbuf, Ws, bs, out);
    (void)in_sizes; (void)n_in; (void)out_size;
}

// round 10
// speedup vs baseline: 1.5240x; 1.2224x over previous
#include <cuda_runtime.h>
#include <cuda_fp16.h>
#include <math.h>
#include <stdint.h>

// ---------------------------------------------------------------------------
// Problem constants
// ---------------------------------------------------------------------------
#define R_ALL 49152      // B*M*NVIEW
#define EMBED 1024
#define INDIM 256
#define HID   256
#define BMR   8192       // B*M
#define NSEQ  6
#define G4    1024       // 4*HID
#define LAYERS 3
#define BATCH 32
#define MROWS 256

// Weight arena offsets (elements)
#define WC_OFF   0
#define WIN_OFF  1048576
#define WIH_OFF  1310720
#define WHH_OFF  2097152
#define W_TOTAL  2883584

// ---------------------------------------------------------------------------
// Scratch (device globals: allocation-free, graph-capturable)
// ---------------------------------------------------------------------------
__device__ float g_big [(size_t)R_ALL * EMBED];     // Gin (fp32, gate-interleaved)
__device__ float g_c   [(size_t)BMR * HID];         // cell state
__device__ float g_v   [R_ALL];
__device__ float g_bsum[LAYERS * G4];               // permuted bih+bhh

__device__ __align__(16) __half g_whi[W_TOTAL];     // weight hi (LSTM W gate-interleaved)
__device__ __align__(16) __half g_wlo[W_TOTAL];     // weight lo (used for Whh only)
__device__ __align__(16) __half g_ach [(size_t)R_ALL * EMBED];  // conv fp16
__device__ __align__(16) __half g_bigh[(size_t)R_ALL * EMBED];  // stage1 out fp16
__device__ __align__(16) __half g_xh  [(size_t)R_ALL * INDIM];  // xseq fp16

// ---------------------------------------------------------------------------
// Helpers
// ---------------------------------------------------------------------------
__device__ __forceinline__ uint32_t smem_u32(const void* p) {
    uint32_t a;
    asm("{ .reg .u64 t; cvta.to.shared.u64 t, %1; cvt.u32.u64 %0, t; }"
        : "=r"(a) : "l"(p));
    return a;
}

#define CP16(dst, src) \
    asm volatile("cp.async.cg.shared.global [%0], [%1], 16;" :: "r"(dst), "l"(src))
#define CP_COMMIT() asm volatile("cp.async.commit_group;")
#define CP_WAIT1()  asm volatile("cp.async.wait_group 1;")

__device__ __forceinline__ void ldmatrix_x4(uint32_t& r0, uint32_t& r1,
                                            uint32_t& r2, uint32_t& r3,
                                            uint32_t addr) {
    asm volatile("ldmatrix.sync.aligned.m8n8.x4.shared.b16 {%0,%1,%2,%3}, [%4];"
                 : "=r"(r0), "=r"(r1), "=r"(r2), "=r"(r3) : "r"(addr));
}

__device__ __forceinline__ void mma_fp16(float* c, const uint32_t* a,
                                         uint32_t b0, uint32_t b1) {
    asm volatile(
        "mma.sync.aligned.m16n8k16.row.col.f32.f16.f16.f32 "
        "{%0,%1,%2,%3}, {%4,%5,%6,%7}, {%8,%9}, {%0,%1,%2,%3};"
        : "+f"(c[0]), "+f"(c[1]), "+f"(c[2]), "+f"(c[3])
        : "r"(a[0]), "r"(a[1]), "r"(a[2]), "r"(a[3]), "r"(b0), "r"(b1));
}

__device__ __forceinline__ float gelu_exact(float x) {
    return 0.5f * x * (1.0f + erff(x * 0.70710678118654752f));
}
__device__ __forceinline__ float sigm(float x) { return 1.0f / (1.0f + expf(-x)); }

// ---------------------------------------------------------------------------
// Prep kernels
// ---------------------------------------------------------------------------
__global__ void convert_act(const float* __restrict__ src,
                            __half* __restrict__ dst, int n4)
{
    int i = blockIdx.x * blockDim.x + threadIdx.x;
    if (i >= n4) return;
    float4 v = ((const float4*)src)[i];
    __half2* d = (__half2*)(dst + (size_t)i * 4);
    d[0] = __floats2half2_rn(v.x, v.y);
    d[1] = __floats2half2_rn(v.z, v.w);
}

// All four weight tensors -> fp16 hi (+lo for Whh) arena
// (LSTM weights gate-interleaved: row r -> (r&255)*4 + (r>>8))
__global__ void convert_weights(const float* __restrict__ Wc,
                                const float* __restrict__ Win,
                                const float* __restrict__ Wih,
                                const float* __restrict__ Whh,
                                __half* __restrict__ dh,
                                __half* __restrict__ dl)
{
    int id = blockIdx.x * blockDim.x + threadIdx.x;   // one float4 per thread
    if (id >= W_TOTAL / 4) return;
    const float* src;
    size_t doff;
    bool need_lo = false;
    if (id < 262144) {                       // Wc 1024x1024
        src  = Wc + (size_t)id * 4;
        doff = WC_OFF + (size_t)id * 4;
    } else if (id < 327680) {                // Win 256x1024
        int lid = id - 262144;
        src  = Win + (size_t)lid * 4;
        doff = WIN_OFF + (size_t)lid * 4;
    } else if (id < 524288) {                // Wih 3 x 1024x256, gate-interleave
        int lid = id - 327680;
        int l   = lid >> 16;
        int rem = lid & 65535;
        int r   = rem >> 6;
        int kk  = (rem & 63) << 2;
        int nr  = (r & 255) * 4 + (r >> 8);
        src  = Wih + (size_t)l * G4 * INDIM + (size_t)r * INDIM + kk;
        doff = WIH_OFF + (size_t)l * G4 * INDIM + (size_t)nr * INDIM + kk;
    } else {                                 // Whh 3 x 1024x256, gate-interleave
        int lid = id - 524288;
        int l   = lid >> 16;
        int rem = lid & 65535;
        int r   = rem >> 6;
        int kk  = (rem & 63) << 2;
        int nr  = (r & 255) * 4 + (r >> 8);
        src  = Whh + (size_t)l * G4 * HID + (size_t)r * HID + kk;
        doff = WHH_OFF + (size_t)l * G4 * HID + (size_t)nr * HID + kk;
        need_lo = true;
    }
    float4 v = *(const float4*)src;
    __half h0 = __float2half(v.x), h1 = __float2half(v.y);
    __half h2 = __float2half(v.z), h3 = __float2half(v.w);
    __half2* ph = (__half2*)(dh + doff);
    ph[0] = __halves2half2(h0, h1);
    ph[1] = __halves2half2(h2, h3);
    if (need_lo) {
        __half2* pl = (__half2*)(dl + doff);
        pl[0] = __floats2half2_rn(v.x - __half2float(h0), v.y - __half2float(h1));
        pl[1] = __floats2half2_rn(v.z - __half2float(h2), v.w - __half2float(h3));
    }
}

// bsum[l, u*4+g] = bih[l, g*256+u] + bhh[l, g*256+u]
__global__ void bias_perm(const float* __restrict__ bih,
                          const float* __restrict__ bhh,
                          float* __restrict__ bsum)
{
    int idx = blockIdx.x * blockDim.x + threadIdx.x;
    if (idx >= LAYERS * G4) return;
    int l = idx >> 10;
    int r = idx & 1023;
    int nr = (r & 255) * 4 + (r >> 8);
    bsum[l * G4 + nr] = bih[idx] + bhh[idx];
}

// ---------------------------------------------------------------------------
// GEMM: C[m][n] = sum_k A[m][k] * W[n][k] (+ epilogue)
// WSPLIT 0: W = Wh fp16 (1 MMA per k16).  B tile: 128 rows x 64 fp16 (128B).
// WSPLIT 1: W = Wh + Wl (2 MMAs per k16). B tile: 2 subtiles x [32hi|32lo].
// Tile 128x128, warptile 32x64 (8 warps 4x2), KC=64, 2-stage cp.async.
// Distinct-accumulator MMA batching (reuse distance 16).
//
// MATH 0: val = acc + bias1[n]
// MATH 1: val = D + gelu(acc + bias1[n])
// MATH 4: fused LSTM cell (gate-interleaved cols; D = Gin slice)
// OUT 0: fp32 C;  OUT 1: fp16 C
// ---------------------------------------------------------------------------
#define TILE_M 128
#define TILE_N 128
#define KC2 64
#define STG0 32768               // WSPLIT=0: A 16KB + B 16KB
#define STG1 49152               // WSPLIT=1: A 16KB + B 32KB
#define SMEM0 (2 * STG0)
#define SMEM1 (2 * STG1)

template<int MATH, int OUT, int WSPLIT>
__global__ void __launch_bounds__(256, 2)
fgemm(const __half* __restrict__ A, int lda,
      const __half* __restrict__ Wh, const __half* __restrict__ Wl,
      int ldw, int K,
      float* __restrict__ Cf, __half* __restrict__ Ch, int ldc,
      const float* __restrict__ bias1,
      const float* __restrict__ D, int ldd,
      float* __restrict__ cst, __half* __restrict__ Xh, int t)
{
    extern __shared__ __align__(128) unsigned char dsm[];
    const uint32_t sbase = smem_u32(dsm);
    const uint32_t stgBytes = WSPLIT ? STG1 : STG0;

    const int tid  = threadIdx.x;
    const int wid  = tid >> 5;
    const int lane = tid & 31;
    const int wm   = wid & 3;        // warp row: 32 m
    const int wn   = wid >> 2;       // warp col: 64 n
    const int m0   = blockIdx.y * TILE_M;
    const int n0   = blockIdx.x * TILE_N;
    const int KT2  = K / KC2;

    float acc[2][8][4];
    #pragma unroll
    for (int i = 0; i < 2; i++)
        #pragma unroll
        for (int j = 0; j < 8; j++)
            #pragma unroll
            for (int q = 0; q < 4; q++) acc[i][j][q] = 0.0f;

    auto stage_issue = [&](int kt2) {
        if (kt2 < KT2) {
            const uint32_t soff = (uint32_t)(kt2 & 1) * stgBytes;
            const int k0 = kt2 * KC2;
            #pragma unroll
            for (int i = 0; i < 4; ++i) {            // A: 1024 16B chunks
                int id  = tid + (i << 8);
                int row = id >> 3, c = id & 7;
                const __half* src = A + (size_t)(m0 + row) * lda + k0 + (c << 3);
                uint32_t dst = sbase + soff + (uint32_t)(row * 128)
                             + (uint32_t)((c ^ (row & 7)) << 4);
                CP16(dst, src);
            }
            if (WSPLIT == 0) {
                #pragma unroll
                for (int i = 0; i < 4; ++i) {        // B: 1024 chunks, hi only
                    int id  = tid + (i << 8);
                    int row = id >> 3, c = id & 7;
                    const __half* src = Wh + (size_t)(n0 + row) * ldw + k0 + (c << 3);
                    uint32_t dst = sbase + soff + 16384u + (uint32_t)(row * 128)
                                 + (uint32_t)((c ^ (row & 7)) << 4);
                    CP16(dst, src);
                }
            } else {
                #pragma unroll
                for (int i = 0; i < 8; ++i) {        // B: 2048 chunks hi+lo
                    int id  = tid + (i << 8);
                    int sub = id >> 10;
                    int rid = id & 1023;
                    int row = rid >> 3, c = rid & 7;
                    int kk  = k0 + sub * 32;
                    const __half* src = (c < 4)
                        ? Wh + (size_t)(n0 + row) * ldw + kk + (c << 3)
                        : Wl + (size_t)(n0 + row) * ldw + kk + ((c - 4) << 3);
                    uint32_t dst = sbase + soff + 16384u + (uint32_t)(sub << 14)
                                 + (uint32_t)(row * 128)
                                 + (uint32_t)((c ^ (row & 7)) << 4);
                    CP16(dst, src);
                }
            }
        }
        CP_COMMIT();
    };

    stage_issue(0);

    const int lrow = lane & 15;
    const int lk3  = (lane >> 4);       // 0/1: k8 half within k16

    const int arow[2] = { wm * 32 + lrow, wm * 32 + 16 + lrow };
    const int brow[4] = { wn * 64 + lrow,      wn * 64 + 16 + lrow,
                          wn * 64 + 32 + lrow, wn * 64 + 48 + lrow };

    for (int kt2 = 0; kt2 < KT2; ++kt2) {
        stage_issue(kt2 + 1);
        CP_WAIT1();
        __syncthreads();

        const uint32_t aBase = sbase + (uint32_t)(kt2 & 1) * stgBytes;

        #pragma unroll
        for (int ks = 0; ks < 4; ++ks) {
            const int chunkA = ks * 2 + lk3;                 // 0..7

            // A fragments
            uint32_t af[2][4];
            #pragma unroll
            for (int mt = 0; mt < 2; ++mt) {
                const int r = arow[mt];
                ldmatrix_x4(af[mt][0], af[mt][1], af[mt][2], af[mt][3],
                            aBase + (uint32_t)(r * 128)
                                  + (uint32_t)((chunkA ^ (r & 7)) << 4));
            }

            if (WSPLIT == 0) {
                const uint32_t bBase = aBase + 16384u;
                uint32_t bh[4][4];
                #pragma unroll
                for (int p = 0; p < 4; ++p) {
                    const int r = brow[p];
                    ldmatrix_x4(bh[p][0], bh[p][1], bh[p][2], bh[p][3],
                                bBase + (uint32_t)(r * 128)
                                      + (uint32_t)((chunkA ^ (r & 7)) << 4));
                }
                #pragma unroll
                for (int p = 0; p < 4; ++p)
                    #pragma unroll
                    for (int mt = 0; mt < 2; ++mt) {
                        mma_fp16(acc[mt][2 * p],     af[mt], bh[p][0], bh[p][2]);
                        mma_fp16(acc[mt][2 * p + 1], af[mt], bh[p][1], bh[p][3]);
                    }
            } else {
                const int sub    = ks >> 1;
                const int chunkB = (ks & 1) * 2 + lk3;       // 0..3 hi; +4 lo
                const uint32_t bBase = aBase + 16384u + (uint32_t)(sub << 14);

                uint32_t bh[4][4];
                #pragma unroll
                for (int p = 0; p < 4; ++p) {
                    const int r = brow[p];
                    ldmatrix_x4(bh[p][0], bh[p][1], bh[p][2], bh[p][3],
                                bBase + (uint32_t)(r * 128)
                                      + (uint32_t)((chunkB ^ (r & 7)) << 4));
                }
                #pragma unroll
                for (int p = 0; p < 4; ++p)
                    #pragma unroll
                    for (int mt = 0; mt < 2; ++mt) {
                        mma_fp16(acc[mt][2 * p],     af[mt], bh[p][0], bh[p][2]);
                        mma_fp16(acc[mt][2 * p + 1], af[mt], bh[p][1], bh[p][3]);
                    }
                uint32_t bl[4][4];
                #pragma unroll
                for (int p = 0; p < 4; ++p) {
                    const int r = brow[p];
                    ldmatrix_x4(bl[p][0], bl[p][1], bl[p][2], bl[p][3],
                                bBase + (uint32_t)(r * 128)
                                      + (uint32_t)(((chunkB + 4) ^ (r & 7)) << 4));
                }
                #pragma unroll
                for (int p = 0; p < 4; ++p)
                    #pragma unroll
                    for (int mt = 0; mt < 2; ++mt) {
                        mma_fp16(acc[mt][2 * p],     af[mt], bl[p][0], bl[p][2]);
                        mma_fp16(acc[mt][2 * p + 1], af[mt], bl[p][1], bl[p][3]);
                    }
            }
        }
        __syncthreads();
    }

    // ---- epilogue ----
    const int qrow = lane >> 2;            // 0..7
    const int qcol = (lane & 3) << 1;      // 0,2,4,6
    #pragma unroll
    for (int mt = 0; mt < 2; ++mt) {
        const int gm = m0 + wm * 32 + mt * 16 + qrow;
        #pragma unroll
        for (int nt = 0; nt < 8; ++nt) {
            const int gn = n0 + wn * 64 + nt * 8 + qcol;
            float c0 = acc[mt][nt][0], c1 = acc[mt][nt][1];
            float c2 = acc[mt][nt][2], c3 = acc[mt][nt][3];

            if (MATH == 4) {
                // fused LSTM cell (gate-interleaved columns)
                float2 d0 = *(const float2*)(D + (size_t)gm * ldd + gn);
                float2 d1 = *(const float2*)(D + (size_t)(gm + 8) * ldd + gn);
                float v0 = c0 + d0.x, v1 = c1 + d0.y;
                float v2 = c2 + d1.x, v3 = c3 + d1.y;
                float e0 = __shfl_xor_sync(0xFFFFFFFFu, v0, 1);
                float e1 = __shfl_xor_sync(0xFFFFFFFFu, v1, 1);
                float e2 = __shfl_xor_sync(0xFFFFFFFFu, v2, 1);
                float e3 = __shfl_xor_sync(0xFFFFFFFFu, v3, 1);
                float gi, gf, gg, go; int row;
                if (!(lane & 1)) { gi = v0; gf = v1; gg = e0; go = e1; row = gm; }
                else             { gi = e2; gf = e3; gg = v2; go = v3; row = gm + 8; }
                const int u = gn >> 2;
                const size_t co = (size_t)row * HID + u;
                float cp = cst[co];
                float cn = sigm(gf) * cp + sigm(gi) * tanhf(gg);
                float hn = sigm(go) * tanhf(cn);
                cst[co] = cn;
                Xh[((size_t)row * NSEQ + t) * HID + u] = __float2half(hn);
                continue;
            }

            float2 o0, o1;
            if (MATH == 0) {
                float2 b = *(const float2*)(bias1 + gn);
                o0.x = c0 + b.x; o0.y = c1 + b.y;
                o1.x = c2 + b.x; o1.y = c3 + b.y;
            } else { // MATH 1
                float2 b  = *(const float2*)(bias1 + gn);
                float2 d0 = *(const float2*)(D + (size_t)gm * ldd + gn);
                float2 d1 = *(const float2*)(D + (size_t)(gm + 8) * ldd + gn);
                o0.x = d0.x + gelu_exact(c0 + b.x);
                o0.y = d0.y + gelu_exact(c1 + b.y);
                o1.x = d1.x + gelu_exact(c2 + b.x);
                o1.y = d1.y + gelu_exact(c3 + b.y);
            }
            if (OUT == 0) {
                *(float2*)(Cf + (size_t)gm * ldc + gn)       = o0;
                *(float2*)(Cf + (size_t)(gm + 8) * ldc + gn) = o1;
            } else {
                *(__half2*)(Ch + (size_t)gm * ldc + gn) =
                    __floats2half2_rn(o0.x, o0.y);
                *(__half2*)(Ch + (size_t)(gm + 8) * ldc + gn) =
                    __floats2half2_rn(o1.x, o1.y);
            }
        }
    }
}

// ---------------------------------------------------------------------------
// LSTM t=0 cell on interleaved Gin (h0=c0=0)
// ---------------------------------------------------------------------------
__global__ void lstm_t0(const float* __restrict__ G, int ldg,
                        float* __restrict__ cst, __half* __restrict__ Xh)
{
    int idx = blockIdx.x * blockDim.x + threadIdx.x;
    if (idx >= BMR * HID) return;
    int bm = idx >> 8;
    int u  = idx & 255;
    float4 g = *(const float4*)(G + (size_t)bm * ldg + 4 * u);  // i,f,g,o
    float c = sigm(g.x) * tanhf(g.z);
    float h = sigm(g.w) * tanhf(c);
    cst[idx] = c;
    Xh[(size_t)bm * NSEQ * HID + u] = __float2half(h);
}

// ---------------------------------------------------------------------------
// Heads
// ---------------------------------------------------------------------------
__global__ void viewport_kernel(const __half* __restrict__ X,
                                const float* __restrict__ Wv,
                                const float* __restrict__ bv,
                                float* __restrict__ v)
{
    int warp = blockIdx.x * (blockDim.x >> 5) + (threadIdx.x >> 5);
    int lane = threadIdx.x & 31;
    if (warp >= R_ALL) return;
    const __half* x = X + (size_t)warp * HID;
    float s = 0.0f;
    #pragma unroll
    for (int k = lane; k < HID; k += 32)
        s = fmaf(__half2float(x[k]), Wv[k], s);
    #pragma unroll
    for (int o = 16; o > 0; o >>= 1) s += __shfl_down_sync(0xFFFFFFFFu, s, o);
    if (lane == 0) v[warp] = s + bv[0];
}

__global__ void score_kernel(const float* __restrict__ v,
                             const float* __restrict__ Ws,
                             const float* __restrict__ bs,
                             float* __restrict__ out)
{
    __shared__ float red[256];
    int b = blockIdx.x;
    int m = threadIdx.x;
    const float* vb = v + ((size_t)b * MROWS + m) * NSEQ;
    float s = 0.0f;
    #pragma unroll
    for (int n = 0; n < NSEQ; n++) s = fmaf(vb[n], Ws[n], s);
    red[m] = s;
    __syncthreads();
    for (int st = 128; st > 0; st >>= 1) {
        if (m < st) red[m] += red[m + st];
        __syncthreads();
    }
    if (m == 0) out[b] = bs[0] + red[0] * (1.0f / (float)MROWS);
}

// ---------------------------------------------------------------------------
// Host orchestration
// ---------------------------------------------------------------------------
template<typename T>
static T* sym_addr(const void* symbol)
{
    void* p = nullptr;
    cudaGetSymbolAddress(&p, symbol);
    return (T*)p;
}

extern "C" void kernel_launch(void* const* d_in, const int* in_sizes, int n_in,
                              void* d_out, int out_size)
{
    const float* swin = (const float*)d_in[0];
    const float* conv = (const float*)d_in[1];
    const float* Wc   = (const float*)d_in[2];
    const float* bc   = (const float*)d_in[3];
    const float* Win  = (const float*)d_in[4];
    const float* b_in = (const float*)d_in[5];
    const float* Wih  = (const float*)d_in[6];
    const float* Whh  = (const float*)d_in[7];
    const float* bih  = (const float*)d_in[8];
    const float* bhh  = (const float*)d_in[9];
    const float* Wv   = (const float*)d_in[10];
    const float* bv   = (const float*)d_in[11];
    const float* Ws   = (const float*)d_in[12];
    const float* bs   = (const float*)d_in[13];
    float* out = (float*)d_out;

    float*  big  = sym_addr<float>(g_big);
    float*  cbuf = sym_addr<float>(g_c);
    float*  vbuf = sym_addr<float>(g_v);
    float*  bsum = sym_addr<float>(g_bsum);
    __half* whi  = sym_addr<__half>(g_whi);
    __half* wlo  = sym_addr<__half>(g_wlo);
    __half* ach  = sym_addr<__half>(g_ach);
    __half* bigh = sym_addr<__half>(g_bigh);
    __half* xh   = sym_addr<__half>(g_xh);

    cudaFuncSetAttribute(fgemm<1,1,0>, cudaFuncAttributeMaxDynamicSharedMemorySize, SMEM0);
    cudaFuncSetAttribute(fgemm<0,1,0>, cudaFuncAttributeMaxDynamicSharedMemorySize, SMEM0);
    cudaFuncSetAttribute(fgemm<0,0,0>, cudaFuncAttributeMaxDynamicSharedMemorySize, SMEM0);
    cudaFuncSetAttribute(fgemm<4,0,1>, cudaFuncAttributeMaxDynamicSharedMemorySize, SMEM1);

    const dim3 blk(256);

    // ---- prep (3 launches) ----
    convert_act<<<(R_ALL * EMBED / 4 + 255) / 256, blk>>>(conv, ach, R_ALL * EMBED / 4);
    convert_weights<<<(W_TOTAL / 4 + 255) / 256, blk>>>(Wc, Win, Wih, Whh, whi, wlo);
    bias_perm<<<(LAYERS * G4 + 255) / 256, blk>>>(bih, bhh, bsum);

    // Stage 1: bigh = fp16(swin + gelu(conv @ Wc^T + bc))   K=1024
    {
        dim3 grid(EMBED / TILE_N, R_ALL / TILE_M);
        fgemm<1,1,0><<<grid, blk, SMEM0>>>(ach, EMBED,
                                           whi + WC_OFF, nullptr, EMBED, EMBED,
                                           nullptr, bigh, EMBED,
                                           bc, swin, EMBED,
                                           nullptr, nullptr, 0);
    }
    // Stage 2: xh = fp16(big @ Win^T + b_in)                K=1024
    {
        dim3 grid(INDIM / TILE_N, R_ALL / TILE_M);
        fgemm<0,1,0><<<grid, blk, SMEM0>>>(bigh, EMBED,
                                           whi + WIN_OFF, nullptr, EMBED, EMBED,
                                           nullptr, xh, INDIM,
                                           b_in, nullptr, 0,
                                           nullptr, nullptr, 0);
    }

    for (int l = 0; l < LAYERS; ++l) {
        const __half* Wih_h = whi + WIH_OFF + (size_t)l * G4 * INDIM;
        const __half* Whh_h = whi + WHH_OFF + (size_t)l * G4 * HID;
        const __half* Whh_l = wlo + WHH_OFF + (size_t)l * G4 * HID;

        // Gin = xseq @ Wih^T + (bih+bhh)  (interleaved cols)  K=256
        {
            dim3 grid(G4 / TILE_N, R_ALL / TILE_M);
            fgemm<0,0,0><<<grid, blk, SMEM0>>>(xh, INDIM,
                                               Wih_h, nullptr, INDIM, INDIM,
                                               big, nullptr, G4,
                                               bsum + l * G4, nullptr, 0,
                                               nullptr, nullptr, 0);
        }

        // t = 0: h0 = c0 = 0 -> cell directly on Gin
        lstm_t0<<<(BMR * HID + 255) / 256, blk>>>(big, NSEQ * G4, cbuf, xh);

        // t >= 1: fused recurrent GEMM + cell; A = xseq slot t-1
        for (int t = 1; t < NSEQ; ++t) {
            dim3 grid(G4 / TILE_N, BMR / TILE_M);
            fgemm<4,0,1><<<grid, blk, SMEM1>>>(xh + (size_t)(t - 1) * HID, NSEQ * HID,
                                               Whh_h, Whh_l, HID, HID,
                                               nullptr, nullptr, 0,
                                               nullptr,
                                               big + (size_t)t * G4, NSEQ * G4,
                                               cbuf, xh, t);
        }
    }

    viewport_kernel<<<R_ALL / 8, blk>>>(xh, Wv, bv, vbuf);
    score_kernel<<<BATCH, blk>>>(vbuf, Ws, bs, out);
    (void)in_sizes; (void)n_in; (void)out_size;
}

// round 12
// speedup vs baseline: 1.7467x; 1.1461x over previous
#include <cuda_runtime.h>
#include <cuda_fp16.h>
#include <math.h>
#include <stdint.h>

// ---------------------------------------------------------------------------
// Problem constants
// ---------------------------------------------------------------------------
#define R_ALL 49152      // B*M*NVIEW
#define EMBED 1024
#define INDIM 256
#define HID   256
#define BMR   8192       // B*M
#define NSEQ  6
#define G4    1024       // 4*HID
#define LAYERS 3
#define BATCH 32
#define MROWS 256

// Weight arena offsets (elements)
#define WC_OFF   0
#define WIN_OFF  1048576
#define WIH_OFF  1310720
#define WHH_OFF  2097152
#define W_TOTAL  2883584

// ---------------------------------------------------------------------------
// Scratch (device globals: allocation-free, graph-capturable)
// ---------------------------------------------------------------------------
__device__ float g_big [(size_t)R_ALL * EMBED];     // Gin (fp32, gate-interleaved)
__device__ float g_c   [(size_t)BMR * HID];         // cell state
__device__ float g_v   [R_ALL];
__device__ float g_bsum[LAYERS * G4];               // permuted bih+bhh

__device__ __align__(16) __half g_whi[W_TOTAL];     // fp16 weights (LSTM gate-interleaved)
__device__ __align__(16) __half g_ach [(size_t)R_ALL * EMBED];  // conv fp16
__device__ __align__(16) __half g_bigh[(size_t)R_ALL * EMBED];  // stage1 out fp16
__device__ __align__(16) __half g_xh  [(size_t)R_ALL * INDIM];  // xseq fp16

// ---------------------------------------------------------------------------
// Helpers
// ---------------------------------------------------------------------------
__device__ __forceinline__ uint32_t smem_u32(const void* p) {
    uint32_t a;
    asm("{ .reg .u64 t; cvta.to.shared.u64 t, %1; cvt.u32.u64 %0, t; }"
        : "=r"(a) : "l"(p));
    return a;
}

#define CP16(dst, src) \
    asm volatile("cp.async.cg.shared.global [%0], [%1], 16;" :: "r"(dst), "l"(src))
#define CP_COMMIT() asm volatile("cp.async.commit_group;")
#define CP_WAIT1()  asm volatile("cp.async.wait_group 1;")

__device__ __forceinline__ void ldmatrix_x4(uint32_t& r0, uint32_t& r1,
                                            uint32_t& r2, uint32_t& r3,
                                            uint32_t addr) {
    asm volatile("ldmatrix.sync.aligned.m8n8.x4.shared.b16 {%0,%1,%2,%3}, [%4];"
                 : "=r"(r0), "=r"(r1), "=r"(r2), "=r"(r3) : "r"(addr));
}

__device__ __forceinline__ void mma_fp16(float* c, const uint32_t* a,
                                         uint32_t b0, uint32_t b1) {
    asm volatile(
        "mma.sync.aligned.m16n8k16.row.col.f32.f16.f16.f32 "
        "{%0,%1,%2,%3}, {%4,%5,%6,%7}, {%8,%9}, {%0,%1,%2,%3};"
        : "+f"(c[0]), "+f"(c[1]), "+f"(c[2]), "+f"(c[3])
        : "r"(a[0]), "r"(a[1]), "r"(a[2]), "r"(a[3]), "r"(b0), "r"(b1));
}

__device__ __forceinline__ float gelu_exact(float x) {
    return 0.5f * x * (1.0f + erff(x * 0.70710678118654752f));
}
__device__ __forceinline__ float sigm(float x) { return 1.0f / (1.0f + expf(-x)); }

// ---------------------------------------------------------------------------
// Prep kernels
// ---------------------------------------------------------------------------
__global__ void convert_act(const float* __restrict__ src,
                            __half* __restrict__ dst, int n4)
{
    int i = blockIdx.x * blockDim.x + threadIdx.x;
    if (i >= n4) return;
    float4 v = ((const float4*)src)[i];
    __half2* d = (__half2*)(dst + (size_t)i * 4);
    d[0] = __floats2half2_rn(v.x, v.y);
    d[1] = __floats2half2_rn(v.z, v.w);
}

// All four weight tensors -> fp16 arena (LSTM weights gate-interleaved:
// row r(gate g=r>>8, unit u=r&255) -> u*4+g)
__global__ void convert_weights(const float* __restrict__ Wc,
                                const float* __restrict__ Win,
                                const float* __restrict__ Wih,
                                const float* __restrict__ Whh,
                                __half* __restrict__ dh)
{
    int id = blockIdx.x * blockDim.x + threadIdx.x;   // one float4 per thread
    if (id >= W_TOTAL / 4) return;
    const float* src;
    size_t doff;
    if (id < 262144) {                       // Wc 1024x1024
        src  = Wc + (size_t)id * 4;
        doff = WC_OFF + (size_t)id * 4;
    } else if (id < 327680) {                // Win 256x1024
        int lid = id - 262144;
        src  = Win + (size_t)lid * 4;
        doff = WIN_OFF + (size_t)lid * 4;
    } else if (id < 524288) {                // Wih 3 x 1024x256, gate-interleave
        int lid = id - 327680;
        int l   = lid >> 16;
        int rem = lid & 65535;
        int r   = rem >> 6;
        int kk  = (rem & 63) << 2;
        int nr  = (r & 255) * 4 + (r >> 8);
        src  = Wih + (size_t)l * G4 * INDIM + (size_t)r * INDIM + kk;
        doff = WIH_OFF + (size_t)l * G4 * INDIM + (size_t)nr * INDIM + kk;
    } else {                                 // Whh 3 x 1024x256, gate-interleave
        int lid = id - 524288;
        int l   = lid >> 16;
        int rem = lid & 65535;
        int r   = rem >> 6;
        int kk  = (rem & 63) << 2;
        int nr  = (r & 255) * 4 + (r >> 8);
        src  = Whh + (size_t)l * G4 * HID + (size_t)r * HID + kk;
        doff = WHH_OFF + (size_t)l * G4 * HID + (size_t)nr * HID + kk;
    }
    float4 v = *(const float4*)src;
    __half2* ph = (__half2*)(dh + doff);
    ph[0] = __floats2half2_rn(v.x, v.y);
    ph[1] = __floats2half2_rn(v.z, v.w);
}

// bsum[l, u*4+g] = bih[l, g*256+u] + bhh[l, g*256+u]
__global__ void bias_perm(const float* __restrict__ bih,
                          const float* __restrict__ bhh,
                          float* __restrict__ bsum)
{
    int idx = blockIdx.x * blockDim.x + threadIdx.x;
    if (idx >= LAYERS * G4) return;
    int l = idx >> 10;
    int r = idx & 1023;
    int nr = (r & 255) * 4 + (r >> 8);
    bsum[l * G4 + nr] = bih[idx] + bhh[idx];
}

// ---------------------------------------------------------------------------
// GEMM: C[m][n] = sum_k A[m][k] * W[n][k] (+ epilogue)  — fp16 weights
// Tile 128x128, warptile 32x64 (8 warps 4x2), KC=64, 2-stage cp.async.
// Distinct-accumulator MMA batching.  Stage 32KB: A 16KB + B 16KB,
// rows 128B, XOR swizzle chunk c -> c^(row&7).
//
// MATH 0: val = acc + bias1[n]                          (store)
// MATH 1: val = D + gelu(acc + bias1[n])                (store)
// MATH 4: fused LSTM cell t>=1 (gate-interleaved cols; D = Gin slice)
// OUT 0: fp32 C;  OUT 1: fp16 C
// ---------------------------------------------------------------------------
#define TILE_M 128
#define TILE_N 128
#define KC2 64
#define STG_BYTES 32768
#define SMEM_DYN (2 * STG_BYTES)

template<int MATH, int OUT>
__global__ void __launch_bounds__(256, 2)
fgemm(const __half* __restrict__ A, int lda,
      const __half* __restrict__ Wh, int ldw, int K,
      float* __restrict__ Cf, __half* __restrict__ Ch, int ldc,
      const float* __restrict__ bias1,
      const float* __restrict__ D, int ldd,
      float* __restrict__ cst, __half* __restrict__ Xh, int t)
{
    extern __shared__ __align__(128) unsigned char dsm[];
    const uint32_t sbase = smem_u32(dsm);

    const int tid  = threadIdx.x;
    const int wid  = tid >> 5;
    const int lane = tid & 31;
    const int wm   = wid & 3;        // warp row: 32 m
    const int wn   = wid >> 2;       // warp col: 64 n
    const int m0   = blockIdx.y * TILE_M;
    const int n0   = blockIdx.x * TILE_N;
    const int KT2  = K / KC2;

    float acc[2][8][4];
    #pragma unroll
    for (int i = 0; i < 2; i++)
        #pragma unroll
        for (int j = 0; j < 8; j++)
            #pragma unroll
            for (int q = 0; q < 4; q++) acc[i][j][q] = 0.0f;

    auto stage_issue = [&](int kt2) {
        if (kt2 < KT2) {
            const uint32_t soff = (uint32_t)(kt2 & 1) * STG_BYTES;
            const int k0 = kt2 * KC2;
            #pragma unroll
            for (int i = 0; i < 4; ++i) {            // A: 1024 16B chunks
                int id  = tid + (i << 8);
                int row = id >> 3, c = id & 7;
                const __half* src = A + (size_t)(m0 + row) * lda + k0 + (c << 3);
                uint32_t dst = sbase + soff + (uint32_t)(row * 128)
                             + (uint32_t)((c ^ (row & 7)) << 4);
                CP16(dst, src);
            }
            #pragma unroll
            for (int i = 0; i < 4; ++i) {            // B: 1024 chunks
                int id  = tid + (i << 8);
                int row = id >> 3, c = id & 7;
                const __half* src = Wh + (size_t)(n0 + row) * ldw + k0 + (c << 3);
                uint32_t dst = sbase + soff + 16384u + (uint32_t)(row * 128)
                             + (uint32_t)((c ^ (row & 7)) << 4);
                CP16(dst, src);
            }
        }
        CP_COMMIT();
    };

    stage_issue(0);

    const int lrow = lane & 15;
    const int lk3  = (lane >> 4);       // 0/1: k8 half within k16

    const int arow[2] = { wm * 32 + lrow, wm * 32 + 16 + lrow };
    const int brow[4] = { wn * 64 + lrow,      wn * 64 + 16 + lrow,
                          wn * 64 + 32 + lrow, wn * 64 + 48 + lrow };

    for (int kt2 = 0; kt2 < KT2; ++kt2) {
        stage_issue(kt2 + 1);
        CP_WAIT1();
        __syncthreads();

        const uint32_t aBase = sbase + (uint32_t)(kt2 & 1) * STG_BYTES;
        const uint32_t bBase = aBase + 16384u;

        #pragma unroll
        for (int ks = 0; ks < 4; ++ks) {
            const int chunkA = ks * 2 + lk3;                 // 0..7

            uint32_t af[2][4];
            #pragma unroll
            for (int mt = 0; mt < 2; ++mt) {
                const int r = arow[mt];
                ldmatrix_x4(af[mt][0], af[mt][1], af[mt][2], af[mt][3],
                            aBase + (uint32_t)(r * 128)
                                  + (uint32_t)((chunkA ^ (r & 7)) << 4));
            }
            uint32_t bh[4][4];
            #pragma unroll
            for (int p = 0; p < 4; ++p) {
                const int r = brow[p];
                ldmatrix_x4(bh[p][0], bh[p][1], bh[p][2], bh[p][3],
                            bBase + (uint32_t)(r * 128)
                                  + (uint32_t)((chunkA ^ (r & 7)) << 4));
            }
            #pragma unroll
            for (int p = 0; p < 4; ++p)
                #pragma unroll
                for (int mt = 0; mt < 2; ++mt) {
                    mma_fp16(acc[mt][2 * p],     af[mt], bh[p][0], bh[p][2]);
                    mma_fp16(acc[mt][2 * p + 1], af[mt], bh[p][1], bh[p][3]);
                }
        }
        __syncthreads();
    }

    // ---- epilogue ----
    const int qrow = lane >> 2;            // 0..7
    const int qcol = (lane & 3) << 1;      // 0,2,4,6
    #pragma unroll
    for (int mt = 0; mt < 2; ++mt) {
        const int gm = m0 + wm * 32 + mt * 16 + qrow;
        #pragma unroll
        for (int nt = 0; nt < 8; ++nt) {
            const int gn = n0 + wn * 64 + nt * 8 + qcol;
            float c0 = acc[mt][nt][0], c1 = acc[mt][nt][1];
            float c2 = acc[mt][nt][2], c3 = acc[mt][nt][3];

            if (MATH == 4) {
                // fused LSTM cell, t >= 1 (rows are bm directly)
                float2 d0 = *(const float2*)(D + (size_t)gm * ldd + gn);
                float2 d1 = *(const float2*)(D + (size_t)(gm + 8) * ldd + gn);
                float v0 = c0 + d0.x, v1 = c1 + d0.y;
                float v2 = c2 + d1.x, v3 = c3 + d1.y;
                float e0 = __shfl_xor_sync(0xFFFFFFFFu, v0, 1);
                float e1 = __shfl_xor_sync(0xFFFFFFFFu, v1, 1);
                float e2 = __shfl_xor_sync(0xFFFFFFFFu, v2, 1);
                float e3 = __shfl_xor_sync(0xFFFFFFFFu, v3, 1);
                float gi, gf, gg, go; int row;
                if (!(lane & 1)) { gi = v0; gf = v1; gg = e0; go = e1; row = gm; }
                else             { gi = e2; gf = e3; gg = v2; go = v3; row = gm + 8; }
                const int u = gn >> 2;
                const size_t co = (size_t)row * HID + u;
                float cp = cst[co];
                float cn = sigm(gf) * cp + sigm(gi) * tanhf(gg);
                float hn = sigm(go) * tanhf(cn);
                cst[co] = cn;
                Xh[((size_t)row * NSEQ + t) * HID + u] = __float2half(hn);
                continue;
            }

            float2 o0, o1;
            if (MATH == 0) {
                float2 b = *(const float2*)(bias1 + gn);
                o0.x = c0 + b.x; o0.y = c1 + b.y;
                o1.x = c2 + b.x; o1.y = c3 + b.y;
            } else { // MATH 1
                float2 b  = *(const float2*)(bias1 + gn);
                float2 d0 = *(const float2*)(D + (size_t)gm * ldd + gn);
                float2 d1 = *(const float2*)(D + (size_t)(gm + 8) * ldd + gn);
                o0.x = d0.x + gelu_exact(c0 + b.x);
                o0.y = d0.y + gelu_exact(c1 + b.y);
                o1.x = d1.x + gelu_exact(c2 + b.x);
                o1.y = d1.y + gelu_exact(c3 + b.y);
            }
            if (OUT == 0) {
                *(float2*)(Cf + (size_t)gm * ldc + gn)       = o0;
                *(float2*)(Cf + (size_t)(gm + 8) * ldc + gn) = o1;
            } else {
                *(__half2*)(Ch + (size_t)gm * ldc + gn) =
                    __floats2half2_rn(o0.x, o0.y);
                *(__half2*)(Ch + (size_t)(gm + 8) * ldc + gn) =
                    __floats2half2_rn(o1.x, o1.y);
            }
        }
    }
}

// ---------------------------------------------------------------------------
// LSTM t=0 cell on interleaved Gin (h0=c0=0)
// ---------------------------------------------------------------------------
__global__ void lstm_t0(const float* __restrict__ G, int ldg,
                        float* __restrict__ cst, __half* __restrict__ Xh)
{
    int idx = blockIdx.x * blockDim.x + threadIdx.x;
    if (idx >= BMR * HID) return;
    int bm = idx >> 8;
    int u  = idx & 255;
    float4 g = *(const float4*)(G + (size_t)bm * ldg + 4 * u);  // i,f,g,o
    float c = sigm(g.x) * tanhf(g.z);
    float h = sigm(g.w) * tanhf(c);
    cst[idx] = c;
    Xh[(size_t)bm * NSEQ * HID + u] = __float2half(h);
}

// ---------------------------------------------------------------------------
// Heads
// ---------------------------------------------------------------------------
__global__ void viewport_kernel(const __half* __restrict__ X,
                                const float* __restrict__ Wv,
                                const float* __restrict__ bv,
                                float* __restrict__ v)
{
    int warp = blockIdx.x * (blockDim.x >> 5) + (threadIdx.x >> 5);
    int lane = threadIdx.x & 31;
    if (warp >= R_ALL) return;
    const __half* x = X + (size_t)warp * HID;
    float s = 0.0f;
    #pragma unroll
    for (int k = lane; k < HID; k += 32)
        s = fmaf(__half2float(x[k]), Wv[k], s);
    #pragma unroll
    for (int o = 16; o > 0; o >>= 1) s += __shfl_down_sync(0xFFFFFFFFu, s, o);
    if (lane == 0) v[warp] = s + bv[0];
}

__global__ void score_kernel(const float* __restrict__ v,
                             const float* __restrict__ Ws,
                             const float* __restrict__ bs,
                             float* __restrict__ out)
{
    __shared__ float red[256];
    int b = blockIdx.x;
    int m = threadIdx.x;
    const float* vb = v + ((size_t)b * MROWS + m) * NSEQ;
    float s = 0.0f;
    #pragma unroll
    for (int n = 0; n < NSEQ; n++) s = fmaf(vb[n], Ws[n], s);
    red[m] = s;
    __syncthreads();
    for (int st = 128; st > 0; st >>= 1) {
        if (m < st) red[m] += red[m + st];
        __syncthreads();
    }
    if (m == 0) out[b] = bs[0] + red[0] * (1.0f / (float)MROWS);
}

// ---------------------------------------------------------------------------
// Host orchestration
// ---------------------------------------------------------------------------
template<typename T>
static T* sym_addr(const void* symbol)
{
    void* p = nullptr;
    cudaGetSymbolAddress(&p, symbol);
    return (T*)p;
}

extern "C" void kernel_launch(void* const* d_in, const int* in_sizes, int n_in,
                              void* d_out, int out_size)
{
    const float* swin = (const float*)d_in[0];
    const float* conv = (const float*)d_in[1];
    const float* Wc   = (const float*)d_in[2];
    const float* bc   = (const float*)d_in[3];
    const float* Win  = (const float*)d_in[4];
    const float* b_in = (const float*)d_in[5];
    const float* Wih  = (const float*)d_in[6];
    const float* Whh  = (const float*)d_in[7];
    const float* bih  = (const float*)d_in[8];
    const float* bhh  = (const float*)d_in[9];
    const float* Wv   = (const float*)d_in[10];
    const float* bv   = (const float*)d_in[11];
    const float* Ws   = (const float*)d_in[12];
    const float* bs   = (const float*)d_in[13];
    float* out = (float*)d_out;

    float*  big  = sym_addr<float>(g_big);
    float*  cbuf = sym_addr<float>(g_c);
    float*  vbuf = sym_addr<float>(g_v);
    float*  bsum = sym_addr<float>(g_bsum);
    __half* whi  = sym_addr<__half>(g_whi);
    __half* ach  = sym_addr<__half>(g_ach);
    __half* bigh = sym_addr<__half>(g_bigh);
    __half* xh   = sym_addr<__half>(g_xh);

    cudaFuncSetAttribute(fgemm<1,1>, cudaFuncAttributeMaxDynamicSharedMemorySize, SMEM_DYN);
    cudaFuncSetAttribute(fgemm<0,1>, cudaFuncAttributeMaxDynamicSharedMemorySize, SMEM_DYN);
    cudaFuncSetAttribute(fgemm<0,0>, cudaFuncAttributeMaxDynamicSharedMemorySize, SMEM_DYN);
    cudaFuncSetAttribute(fgemm<4,0>, cudaFuncAttributeMaxDynamicSharedMemorySize, SMEM_DYN);

    const dim3 blk(256);

    // ---- prep (3 launches) ----
    convert_act<<<(R_ALL * EMBED / 4 + 255) / 256, blk>>>(conv, ach, R_ALL * EMBED / 4);
    convert_weights<<<(W_TOTAL / 4 + 255) / 256, blk>>>(Wc, Win, Wih, Whh, whi);
    bias_perm<<<(LAYERS * G4 + 255) / 256, blk>>>(bih, bhh, bsum);

    // Stage 1: bigh = fp16(swin + gelu(conv @ Wc^T + bc))   K=1024
    {
        dim3 grid(EMBED / TILE_N, R_ALL / TILE_M);
        fgemm<1,1><<<grid, blk, SMEM_DYN>>>(ach, EMBED,
                                            whi + WC_OFF, EMBED, EMBED,
                                            nullptr, bigh, EMBED,
                                            bc, swin, EMBED,
                                            nullptr, nullptr, 0);
    }
    // Stage 2: xh = fp16(big @ Win^T + b_in)                K=1024
    {
        dim3 grid(INDIM / TILE_N, R_ALL / TILE_M);
        fgemm<0,1><<<grid, blk, SMEM_DYN>>>(bigh, EMBED,
                                            whi + WIN_OFF, EMBED, EMBED,
                                            nullptr, xh, INDIM,
                                            b_in, nullptr, 0,
                                            nullptr, nullptr, 0);
    }

    for (int l = 0; l < LAYERS; ++l) {
        const __half* Wih_h = whi + WIH_OFF + (size_t)l * G4 * INDIM;
        const __half* Whh_h = whi + WHH_OFF + (size_t)l * G4 * HID;

        // Gin = xseq @ Wih^T + (bih+bhh)  (interleaved cols)  K=256
        {
            dim3 grid(G4 / TILE_N, R_ALL / TILE_M);
            fgemm<0,0><<<grid, blk, SMEM_DYN>>>(xh, INDIM,
                                                Wih_h, INDIM, INDIM,
                                                big, nullptr, G4,
                                                bsum + l * G4, nullptr, 0,
                                                nullptr, nullptr, 0);
        }

        // t = 0: h0 = c0 = 0 -> cell directly on Gin
        lstm_t0<<<(BMR * HID + 255) / 256, blk>>>(big, NSEQ * G4, cbuf, xh);

        // t >= 1: fused recurrent GEMM + cell; A = xseq slot t-1
        for (int t = 1; t < NSEQ; ++t) {
            dim3 grid(G4 / TILE_N, BMR / TILE_M);
            fgemm<4,0><<<grid, blk, SMEM_DYN>>>(xh + (size_t)(t - 1) * HID, NSEQ * HID,
                                                Whh_h, HID, HID,
                                                nullptr, nullptr, 0,
                                                nullptr,
                                                big + (size_t)t * G4, NSEQ * G4,
                                                cbuf, xh, t);
        }
    }

    viewport_kernel<<<R_ALL / 8, blk>>>(xh, Wv, bv, vbuf);
    score_kernel<<<BATCH, blk>>>(vbuf, Ws, bs, out);
    (void)in_sizes; (void)n_in; (void)out_size;
}

// round 13
// speedup vs baseline: 1.8030x; 1.0322x over previous
#include <cuda_runtime.h>
#include <cuda_fp16.h>
#include <math.h>
#include <stdint.h>

// ---------------------------------------------------------------------------
// Problem constants
// ---------------------------------------------------------------------------
#define R_ALL 49152      // B*M*NVIEW
#define EMBED 1024
#define INDIM 256
#define HID   256
#define BMR   8192       // B*M
#define NSEQ  6
#define G4    1024       // 4*HID
#define LAYERS 3
#define BATCH 32
#define MROWS 256

// Weight arena offsets (elements)
#define WC_OFF   0
#define WIN_OFF  1048576
#define WIH_OFF  1310720
#define WHH_OFF  2097152
#define W_TOTAL  2883584

// ---------------------------------------------------------------------------
// Scratch (device globals: allocation-free, graph-capturable)
// ---------------------------------------------------------------------------
__device__ float g_c   [(size_t)BMR * HID];         // cell state
__device__ float g_v   [R_ALL];
__device__ float g_bsum[LAYERS * G4];               // permuted bih+bhh

__device__ __align__(16) __half g_gin [(size_t)R_ALL * G4];     // Gin fp16 (gate-interleaved)
__device__ __align__(16) __half g_whi[W_TOTAL];     // fp16 weights (LSTM gate-interleaved)
__device__ __align__(16) __half g_ach [(size_t)R_ALL * EMBED];  // conv fp16
__device__ __align__(16) __half g_bigh[(size_t)R_ALL * EMBED];  // stage1 out fp16
__device__ __align__(16) __half g_xh  [(size_t)R_ALL * INDIM];  // xseq fp16

// ---------------------------------------------------------------------------
// Helpers
// ---------------------------------------------------------------------------
__device__ __forceinline__ uint32_t smem_u32(const void* p) {
    uint32_t a;
    asm("{ .reg .u64 t; cvta.to.shared.u64 t, %1; cvt.u32.u64 %0, t; }"
        : "=r"(a) : "l"(p));
    return a;
}

#define CP16(dst, src) \
    asm volatile("cp.async.cg.shared.global [%0], [%1], 16;" :: "r"(dst), "l"(src))
#define CP_COMMIT() asm volatile("cp.async.commit_group;")
#define CP_WAIT1()  asm volatile("cp.async.wait_group 1;")

__device__ __forceinline__ void ldmatrix_x4(uint32_t& r0, uint32_t& r1,
                                            uint32_t& r2, uint32_t& r3,
                                            uint32_t addr) {
    asm volatile("ldmatrix.sync.aligned.m8n8.x4.shared.b16 {%0,%1,%2,%3}, [%4];"
                 : "=r"(r0), "=r"(r1), "=r"(r2), "=r"(r3) : "r"(addr));
}

__device__ __forceinline__ void mma_fp16(float* c, const uint32_t* a,
                                         uint32_t b0, uint32_t b1) {
    asm volatile(
        "mma.sync.aligned.m16n8k16.row.col.f32.f16.f16.f32 "
        "{%0,%1,%2,%3}, {%4,%5,%6,%7}, {%8,%9}, {%0,%1,%2,%3};"
        : "+f"(c[0]), "+f"(c[1]), "+f"(c[2]), "+f"(c[3])
        : "r"(a[0]), "r"(a[1]), "r"(a[2]), "r"(a[3]), "r"(b0), "r"(b1));
}

__device__ __forceinline__ float gelu_exact(float x) {
    return 0.5f * x * (1.0f + erff(x * 0.70710678118654752f));
}
__device__ __forceinline__ float sigm(float x) { return 1.0f / (1.0f + expf(-x)); }

// ---------------------------------------------------------------------------
// Prep kernels
// ---------------------------------------------------------------------------
__global__ void convert_act(const float* __restrict__ src,
                            __half* __restrict__ dst, int n4)
{
    int i = blockIdx.x * blockDim.x + threadIdx.x;
    if (i >= n4) return;
    float4 v = ((const float4*)src)[i];
    __half2* d = (__half2*)(dst + (size_t)i * 4);
    d[0] = __floats2half2_rn(v.x, v.y);
    d[1] = __floats2half2_rn(v.z, v.w);
}

// All four weight tensors -> fp16 arena (LSTM weights gate-interleaved:
// row r(gate g=r>>8, unit u=r&255) -> u*4+g)
__global__ void convert_weights(const float* __restrict__ Wc,
                                const float* __restrict__ Win,
                                const float* __restrict__ Wih,
                                const float* __restrict__ Whh,
                                __half* __restrict__ dh)
{
    int id = blockIdx.x * blockDim.x + threadIdx.x;   // one float4 per thread
    if (id >= W_TOTAL / 4) return;
    const float* src;
    size_t doff;
    if (id < 262144) {                       // Wc 1024x1024
        src  = Wc + (size_t)id * 4;
        doff = WC_OFF + (size_t)id * 4;
    } else if (id < 327680) {                // Win 256x1024
        int lid = id - 262144;
        src  = Win + (size_t)lid * 4;
        doff = WIN_OFF + (size_t)lid * 4;
    } else if (id < 524288) {                // Wih 3 x 1024x256, gate-interleave
        int lid = id - 327680;
        int l   = lid >> 16;
        int rem = lid & 65535;
        int r   = rem >> 6;
        int kk  = (rem & 63) << 2;
        int nr  = (r & 255) * 4 + (r >> 8);
        src  = Wih + (size_t)l * G4 * INDIM + (size_t)r * INDIM + kk;
        doff = WIH_OFF + (size_t)l * G4 * INDIM + (size_t)nr * INDIM + kk;
    } else {                                 // Whh 3 x 1024x256, gate-interleave
        int lid = id - 524288;
        int l   = lid >> 16;
        int rem = lid & 65535;
        int r   = rem >> 6;
        int kk  = (rem & 63) << 2;
        int nr  = (r & 255) * 4 + (r >> 8);
        src  = Whh + (size_t)l * G4 * HID + (size_t)r * HID + kk;
        doff = WHH_OFF + (size_t)l * G4 * HID + (size_t)nr * HID + kk;
    }
    float4 v = *(const float4*)src;
    __half2* ph = (__half2*)(dh + doff);
    ph[0] = __floats2half2_rn(v.x, v.y);
    ph[1] = __floats2half2_rn(v.z, v.w);
}

// bsum[l, u*4+g] = bih[l, g*256+u] + bhh[l, g*256+u]
__global__ void bias_perm(const float* __restrict__ bih,
                          const float* __restrict__ bhh,
                          float* __restrict__ bsum)
{
    int idx = blockIdx.x * blockDim.x + threadIdx.x;
    if (idx >= LAYERS * G4) return;
    int l = idx >> 10;
    int r = idx & 1023;
    int nr = (r & 255) * 4 + (r >> 8);
    bsum[l * G4 + nr] = bih[idx] + bhh[idx];
}

// ---------------------------------------------------------------------------
// GEMM: C[m][n] = sum_k A[m][k] * W[n][k] (+ epilogue)  — fp16 weights
// Tile 128x128, warptile 32x64 (8 warps 4x2), KC=64, 2-stage cp.async.
// Distinct-accumulator MMA batching.  Stage 32KB: A 16KB + B 16KB,
// rows 128B, XOR swizzle chunk c -> c^(row&7).
//
// MATH 0: val = acc + bias1[n]                          (store)
// MATH 1: val = D + gelu(acc + bias1[n])                (store; D fp32)
// MATH 4: fused LSTM cell t>=1 (gate-interleaved cols; Dh = fp16 Gin slice)
// OUT 0: fp32 C;  OUT 1: fp16 C
// ---------------------------------------------------------------------------
#define TILE_M 128
#define TILE_N 128
#define KC2 64
#define STG_BYTES 32768
#define SMEM_DYN (2 * STG_BYTES)

template<int MATH, int OUT>
__global__ void __launch_bounds__(256, 2)
fgemm(const __half* __restrict__ A, int lda,
      const __half* __restrict__ Wh, int ldw, int K,
      float* __restrict__ Cf, __half* __restrict__ Ch, int ldc,
      const float* __restrict__ bias1,
      const float* __restrict__ D, const __half* __restrict__ Dh, int ldd,
      float* __restrict__ cst, __half* __restrict__ Xh, int t)
{
    extern __shared__ __align__(128) unsigned char dsm[];
    const uint32_t sbase = smem_u32(dsm);

    const int tid  = threadIdx.x;
    const int wid  = tid >> 5;
    const int lane = tid & 31;
    const int wm   = wid & 3;        // warp row: 32 m
    const int wn   = wid >> 2;       // warp col: 64 n
    const int m0   = blockIdx.y * TILE_M;
    const int n0   = blockIdx.x * TILE_N;
    const int KT2  = K / KC2;

    float acc[2][8][4];
    #pragma unroll
    for (int i = 0; i < 2; i++)
        #pragma unroll
        for (int j = 0; j < 8; j++)
            #pragma unroll
            for (int q = 0; q < 4; q++) acc[i][j][q] = 0.0f;

    auto stage_issue = [&](int kt2) {
        if (kt2 < KT2) {
            const uint32_t soff = (uint32_t)(kt2 & 1) * STG_BYTES;
            const int k0 = kt2 * KC2;
            #pragma unroll
            for (int i = 0; i < 4; ++i) {            // A: 1024 16B chunks
                int id  = tid + (i << 8);
                int row = id >> 3, c = id & 7;
                const __half* src = A + (size_t)(m0 + row) * lda + k0 + (c << 3);
                uint32_t dst = sbase + soff + (uint32_t)(row * 128)
                             + (uint32_t)((c ^ (row & 7)) << 4);
                CP16(dst, src);
            }
            #pragma unroll
            for (int i = 0; i < 4; ++i) {            // B: 1024 chunks
                int id  = tid + (i << 8);
                int row = id >> 3, c = id & 7;
                const __half* src = Wh + (size_t)(n0 + row) * ldw + k0 + (c << 3);
                uint32_t dst = sbase + soff + 16384u + (uint32_t)(row * 128)
                             + (uint32_t)((c ^ (row & 7)) << 4);
                CP16(dst, src);
            }
        }
        CP_COMMIT();
    };

    stage_issue(0);

    const int lrow = lane & 15;
    const int lk3  = (lane >> 4);       // 0/1: k8 half within k16

    const int arow[2] = { wm * 32 + lrow, wm * 32 + 16 + lrow };
    const int brow[4] = { wn * 64 + lrow,      wn * 64 + 16 + lrow,
                          wn * 64 + 32 + lrow, wn * 64 + 48 + lrow };

    for (int kt2 = 0; kt2 < KT2; ++kt2) {
        stage_issue(kt2 + 1);
        CP_WAIT1();
        __syncthreads();

        const uint32_t aBase = sbase + (uint32_t)(kt2 & 1) * STG_BYTES;
        const uint32_t bBase = aBase + 16384u;

        #pragma unroll
        for (int ks = 0; ks < 4; ++ks) {
            const int chunkA = ks * 2 + lk3;                 // 0..7

            uint32_t af[2][4];
            #pragma unroll
            for (int mt = 0; mt < 2; ++mt) {
                const int r = arow[mt];
                ldmatrix_x4(af[mt][0], af[mt][1], af[mt][2], af[mt][3],
                            aBase + (uint32_t)(r * 128)
                                  + (uint32_t)((chunkA ^ (r & 7)) << 4));
            }
            uint32_t bh[4][4];
            #pragma unroll
            for (int p = 0; p < 4; ++p) {
                const int r = brow[p];
                ldmatrix_x4(bh[p][0], bh[p][1], bh[p][2], bh[p][3],
                            bBase + (uint32_t)(r * 128)
                                  + (uint32_t)((chunkA ^ (r & 7)) << 4));
            }
            #pragma unroll
            for (int p = 0; p < 4; ++p)
                #pragma unroll
                for (int mt = 0; mt < 2; ++mt) {
                    mma_fp16(acc[mt][2 * p],     af[mt], bh[p][0], bh[p][2]);
                    mma_fp16(acc[mt][2 * p + 1], af[mt], bh[p][1], bh[p][3]);
                }
        }
        __syncthreads();
    }

    // ---- epilogue ----
    const int qrow = lane >> 2;            // 0..7
    const int qcol = (lane & 3) << 1;      // 0,2,4,6
    #pragma unroll
    for (int mt = 0; mt < 2; ++mt) {
        const int gm = m0 + wm * 32 + mt * 16 + qrow;
        #pragma unroll
        for (int nt = 0; nt < 8; ++nt) {
            const int gn = n0 + wn * 64 + nt * 8 + qcol;
            float c0 = acc[mt][nt][0], c1 = acc[mt][nt][1];
            float c2 = acc[mt][nt][2], c3 = acc[mt][nt][3];

            if (MATH == 4) {
                // fused LSTM cell, t >= 1 (rows are bm directly); Gin fp16
                float2 d0 = __half22float2(
                    *(const __half2*)(Dh + (size_t)gm * ldd + gn));
                float2 d1 = __half22float2(
                    *(const __half2*)(Dh + (size_t)(gm + 8) * ldd + gn));
                float v0 = c0 + d0.x, v1 = c1 + d0.y;
                float v2 = c2 + d1.x, v3 = c3 + d1.y;
                float e0 = __shfl_xor_sync(0xFFFFFFFFu, v0, 1);
                float e1 = __shfl_xor_sync(0xFFFFFFFFu, v1, 1);
                float e2 = __shfl_xor_sync(0xFFFFFFFFu, v2, 1);
                float e3 = __shfl_xor_sync(0xFFFFFFFFu, v3, 1);
                float gi, gf, gg, go; int row;
                if (!(lane & 1)) { gi = v0; gf = v1; gg = e0; go = e1; row = gm; }
                else             { gi = e2; gf = e3; gg = v2; go = v3; row = gm + 8; }
                const int u = gn >> 2;
                const size_t co = (size_t)row * HID + u;
                float cp = cst[co];
                float cn = sigm(gf) * cp + sigm(gi) * tanhf(gg);
                float hn = sigm(go) * tanhf(cn);
                cst[co] = cn;
                Xh[((size_t)row * NSEQ + t) * HID + u] = __float2half(hn);
                continue;
            }

            float2 o0, o1;
            if (MATH == 0) {
                float2 b = *(const float2*)(bias1 + gn);
                o0.x = c0 + b.x; o0.y = c1 + b.y;
                o1.x = c2 + b.x; o1.y = c3 + b.y;
            } else { // MATH 1
                float2 b  = *(const float2*)(bias1 + gn);
                float2 d0 = *(const float2*)(D + (size_t)gm * ldd + gn);
                float2 d1 = *(const float2*)(D + (size_t)(gm + 8) * ldd + gn);
                o0.x = d0.x + gelu_exact(c0 + b.x);
                o0.y = d0.y + gelu_exact(c1 + b.y);
                o1.x = d1.x + gelu_exact(c2 + b.x);
                o1.y = d1.y + gelu_exact(c3 + b.y);
            }
            if (OUT == 0) {
                *(float2*)(Cf + (size_t)gm * ldc + gn)       = o0;
                *(float2*)(Cf + (size_t)(gm + 8) * ldc + gn) = o1;
            } else {
                *(__half2*)(Ch + (size_t)gm * ldc + gn) =
                    __floats2half2_rn(o0.x, o0.y);
                *(__half2*)(Ch + (size_t)(gm + 8) * ldc + gn) =
                    __floats2half2_rn(o1.x, o1.y);
            }
        }
    }
}

// ---------------------------------------------------------------------------
// LSTM t=0 cell on interleaved fp16 Gin (h0=c0=0)
// ---------------------------------------------------------------------------
__global__ void lstm_t0(const __half* __restrict__ G, int ldg,
                        float* __restrict__ cst, __half* __restrict__ Xh)
{
    int idx = blockIdx.x * blockDim.x + threadIdx.x;
    if (idx >= BMR * HID) return;
    int bm = idx >> 8;
    int u  = idx & 255;
    const __half2* gp = (const __half2*)(G + (size_t)bm * ldg + 4 * u);
    float2 g01 = __half22float2(gp[0]);   // i, f
    float2 g23 = __half22float2(gp[1]);   // g, o
    float c = sigm(g01.x) * tanhf(g23.x);
    float h = sigm(g23.y) * tanhf(c);
    cst[idx] = c;
    Xh[(size_t)bm * NSEQ * HID + u] = __float2half(h);
}

// ---------------------------------------------------------------------------
// Heads
// ---------------------------------------------------------------------------
__global__ void viewport_kernel(const __half* __restrict__ X,
                                const float* __restrict__ Wv,
                                const float* __restrict__ bv,
                                float* __restrict__ v)
{
    int warp = blockIdx.x * (blockDim.x >> 5) + (threadIdx.x >> 5);
    int lane = threadIdx.x & 31;
    if (warp >= R_ALL) return;
    const __half* x = X + (size_t)warp * HID;
    float s = 0.0f;
    #pragma unroll
    for (int k = lane; k < HID; k += 32)
        s = fmaf(__half2float(x[k]), Wv[k], s);
    #pragma unroll
    for (int o = 16; o > 0; o >>= 1) s += __shfl_down_sync(0xFFFFFFFFu, s, o);
    if (lane == 0) v[warp] = s + bv[0];
}

__global__ void score_kernel(const float* __restrict__ v,
                             const float* __restrict__ Ws,
                             const float* __restrict__ bs,
                             float* __restrict__ out)
{
    __shared__ float red[256];
    int b = blockIdx.x;
    int m = threadIdx.x;
    const float* vb = v + ((size_t)b * MROWS + m) * NSEQ;
    float s = 0.0f;
    #pragma unroll
    for (int n = 0; n < NSEQ; n++) s = fmaf(vb[n], Ws[n], s);
    red[m] = s;
    __syncthreads();
    for (int st = 128; st > 0; st >>= 1) {
        if (m < st) red[m] += red[m + st];
        __syncthreads();
    }
    if (m == 0) out[b] = bs[0] + red[0] * (1.0f / (float)MROWS);
}

// ---------------------------------------------------------------------------
// Host orchestration
// ---------------------------------------------------------------------------
template<typename T>
static T* sym_addr(const void* symbol)
{
    void* p = nullptr;
    cudaGetSymbolAddress(&p, symbol);
    return (T*)p;
}

extern "C" void kernel_launch(void* const* d_in, const int* in_sizes, int n_in,
                              void* d_out, int out_size)
{
    const float* swin = (const float*)d_in[0];
    const float* conv = (const float*)d_in[1];
    const float* Wc   = (const float*)d_in[2];
    const float* bc   = (const float*)d_in[3];
    const float* Win  = (const float*)d_in[4];
    const float* b_in = (const float*)d_in[5];
    const float* Wih  = (const float*)d_in[6];
    const float* Whh  = (const float*)d_in[7];
    const float* bih  = (const float*)d_in[8];
    const float* bhh  = (const float*)d_in[9];
    const float* Wv   = (const float*)d_in[10];
    const float* bv   = (const float*)d_in[11];
    const float* Ws   = (const float*)d_in[12];
    const float* bs   = (const float*)d_in[13];
    float* out = (float*)d_out;

    float*  cbuf = sym_addr<float>(g_c);
    float*  vbuf = sym_addr<float>(g_v);
    float*  bsum = sym_addr<float>(g_bsum);
    __half* gin  = sym_addr<__half>(g_gin);
    __half* whi  = sym_addr<__half>(g_whi);
    __half* ach  = sym_addr<__half>(g_ach);
    __half* bigh = sym_addr<__half>(g_bigh);
    __half* xh   = sym_addr<__half>(g_xh);

    cudaFuncSetAttribute(fgemm<1,1>, cudaFuncAttributeMaxDynamicSharedMemorySize, SMEM_DYN);
    cudaFuncSetAttribute(fgemm<0,1>, cudaFuncAttributeMaxDynamicSharedMemorySize, SMEM_DYN);
    cudaFuncSetAttribute(fgemm<4,0>, cudaFuncAttributeMaxDynamicSharedMemorySize, SMEM_DYN);

    const dim3 blk(256);

    // ---- prep (3 launches) ----
    convert_act<<<(R_ALL * EMBED / 4 + 255) / 256, blk>>>(conv, ach, R_ALL * EMBED / 4);
    convert_weights<<<(W_TOTAL / 4 + 255) / 256, blk>>>(Wc, Win, Wih, Whh, whi);
    bias_perm<<<(LAYERS * G4 + 255) / 256, blk>>>(bih, bhh, bsum);

    // Stage 1: bigh = fp16(swin + gelu(conv @ Wc^T + bc))   K=1024
    {
        dim3 grid(EMBED / TILE_N, R_ALL / TILE_M);
        fgemm<1,1><<<grid, blk, SMEM_DYN>>>(ach, EMBED,
                                            whi + WC_OFF, EMBED, EMBED,
                                            nullptr, bigh, EMBED,
                                            bc, swin, nullptr, EMBED,
                                            nullptr, nullptr, 0);
    }
    // Stage 2: xh = fp16(big @ Win^T + b_in)                K=1024
    {
        dim3 grid(INDIM / TILE_N, R_ALL / TILE_M);
        fgemm<0,1><<<grid, blk, SMEM_DYN>>>(bigh, EMBED,
                                            whi + WIN_OFF, EMBED, EMBED,
                                            nullptr, xh, INDIM,
                                            b_in, nullptr, nullptr, 0,
                                            nullptr, nullptr, 0);
    }

    for (int l = 0; l < LAYERS; ++l) {
        const __half* Wih_h = whi + WIH_OFF + (size_t)l * G4 * INDIM;
        const __half* Whh_h = whi + WHH_OFF + (size_t)l * G4 * HID;

        // Gin(fp16) = xseq @ Wih^T + (bih+bhh)  (interleaved cols)  K=256
        {
            dim3 grid(G4 / TILE_N, R_ALL / TILE_M);
            fgemm<0,1><<<grid, blk, SMEM_DYN>>>(xh, INDIM,
                                                Wih_h, INDIM, INDIM,
                                                nullptr, gin, G4,
                                                bsum + l * G4, nullptr, nullptr, 0,
                                                nullptr, nullptr, 0);
        }

        // t = 0: h0 = c0 = 0 -> cell directly on Gin
        lstm_t0<<<(BMR * HID + 255) / 256, blk>>>(gin, NSEQ * G4, cbuf, xh);

        // t >= 1: fused recurrent GEMM + cell; A = xseq slot t-1
        for (int t = 1; t < NSEQ; ++t) {
            dim3 grid(G4 / TILE_N, BMR / TILE_M);
            fgemm<4,0><<<grid, blk, SMEM_DYN>>>(xh + (size_t)(t - 1) * HID, NSEQ * HID,
                                                Whh_h, HID, HID,
                                                nullptr, nullptr, 0,
                                                nullptr,
                                                nullptr, gin + (size_t)t * G4, NSEQ * G4,
                                                cbuf, xh, t);
        }
    }

    viewport_kernel<<<R_ALL / 8, blk>>>(xh, Wv, bv, vbuf);
    score_kernel<<<BATCH, blk>>>(vbuf, Ws, bs, out);
    (void)in_sizes; (void)n_in; (void)out_size;
}